// round 10
// baseline (speedup 1.0000x reference)
#include <cuda_runtime.h>
#include <cuda_bf16.h>
#include <cstdint>

#define T_ 128
#define B_ 512
#define D_ 512
#define H_ 2048
#define C_ 18
#define M_ (T_ * B_)   // 65536

#define CAP 262144           // at-risk neuron capacity (expected ~18k)
#define DELTA 2.5e-4f        // flag margin (~50 sigma of fast-path v-error)

// ---------------- device scratch (allocation-free rule) ----------------
__device__ __nv_bfloat16 g_Ahi[(size_t)M_ * D_];
__device__ __nv_bfloat16 g_Amid[(size_t)M_ * D_];
__device__ __nv_bfloat16 g_Alo[(size_t)M_ * D_];
__device__ __nv_bfloat16 g_Bhi[(size_t)H_ * D_];
__device__ __nv_bfloat16 g_Bmid[(size_t)H_ * D_];
__device__ __nv_bfloat16 g_Blo[(size_t)H_ * D_];
__device__ float g_hall[(size_t)M_ * H_];      // 512 MB (fast h)
__device__ float g_z[B_ * H_];
__device__ unsigned int g_cnt;
__device__ int g_list[CAP];
__device__ float g_hfix[(size_t)CAP * T_];     // 134 MB

// ---------------- helpers ----------------
static __device__ __forceinline__ uint32_t s2u(const void* p) {
    uint32_t a;
    asm("{ .reg .u64 t; cvta.to.shared.u64 t, %1; cvt.u32.u64 %0, t; }" : "=r"(a) : "l"(p));
    return a;
}
#define SWZ(o) ((o) ^ (((o) >> 3) & 0x70))

#define LDSM4(r, a) \
    asm volatile("ldmatrix.sync.aligned.m8n8.x4.shared.b16 {%0,%1,%2,%3}, [%4];" \
                 : "=r"((r)[0]), "=r"((r)[1]), "=r"((r)[2]), "=r"((r)[3]) : "r"(a))

#define MMA16816(d, a, b) \
    asm volatile("mma.sync.aligned.m16n8k16.row.col.f32.bf16.bf16.f32 " \
                 "{%0,%1,%2,%3}, {%4,%5,%6,%7}, {%8,%9}, {%0,%1,%2,%3};" \
                 : "+f"((d)[0]), "+f"((d)[1]), "+f"((d)[2]), "+f"((d)[3]) \
                 : "r"((a)[0]), "r"((a)[1]), "r"((a)[2]), "r"((a)[3]), \
                   "r"((b)[0]), "r"((b)[1]))

// ---------------- split: fp32 -> exact 3-way bf16 ----------------
static __device__ __forceinline__ uint32_t pk(__nv_bfloat16 a, __nv_bfloat16 b) {
    return (uint32_t)__bfloat16_as_ushort(a) | ((uint32_t)__bfloat16_as_ushort(b) << 16);
}

static __device__ __forceinline__ void split4(const float* __restrict__ src,
                                              __nv_bfloat16* __restrict__ hi,
                                              __nv_bfloat16* __restrict__ mid,
                                              __nv_bfloat16* __restrict__ lo,
                                              int i)
{
    float4 v = ((const float4*)src)[i];
    float a[4] = {v.x, v.y, v.z, v.w};
    __nv_bfloat16 h[4], m[4], l[4];
#pragma unroll
    for (int j = 0; j < 4; j++) {
        float x = a[j];
        __nv_bfloat16 xh = __float2bfloat16(x);
        float r1 = x - __bfloat162float(xh);
        __nv_bfloat16 xm = __float2bfloat16(r1);
        float r2 = r1 - __bfloat162float(xm);
        h[j] = xh; m[j] = xm; l[j] = __float2bfloat16(r2);
    }
    uint2 oh, om, ol;
    oh.x = pk(h[0], h[1]); oh.y = pk(h[2], h[3]);
    om.x = pk(m[0], m[1]); om.y = pk(m[2], m[3]);
    ol.x = pk(l[0], l[1]); ol.y = pk(l[2], l[3]);
    *(uint2*)(hi  + 4 * (size_t)i) = oh;
    *(uint2*)(mid + 4 * (size_t)i) = om;
    *(uint2*)(lo  + 4 * (size_t)i) = ol;
}

__global__ void __launch_bounds__(256) splitA_kernel(const float* __restrict__ src) {
    int i = blockIdx.x * blockDim.x + threadIdx.x;
    if (i < M_ * D_ / 4) split4(src, g_Ahi, g_Amid, g_Alo, i);
}
__global__ void __launch_bounds__(256) splitB_kernel(const float* __restrict__ src) {
    int i = blockIdx.x * blockDim.x + threadIdx.x;
    if (i < H_ * D_ / 4) split4(src, g_Bhi, g_Bmid, g_Blo, i);
}

__global__ void zero_cnt_kernel() { g_cnt = 0u; }

// ---------------- fast HMMA GEMM (6-product bf16 split) ----------------
#define TILE_K 64
#define SLAB_BYTES 16384
#define STAGE_BYTES (6 * SLAB_BYTES)
#define SMEM_TOTAL (2 * STAGE_BYTES)   // 192 KB

__global__ void __launch_bounds__(256, 1) gemm_hmma_kernel(const float* __restrict__ bias)
{
    extern __shared__ char smem[];
    const uint32_t sb = s2u(smem);
    const int tid = threadIdx.x;
    const int wid = tid >> 5;
    const int lane = tid & 31;
    const int wm = wid >> 2;
    const int wn = wid & 3;

    const int m0 = (int)blockIdx.y * 128;
    const int n0 = (int)blockIdx.x * 128;

    const __nv_bfloat16* planes[6] = {
        g_Ahi  + (size_t)m0 * D_, g_Amid + (size_t)m0 * D_, g_Alo + (size_t)m0 * D_,
        g_Bhi  + (size_t)n0 * D_, g_Bmid + (size_t)n0 * D_, g_Blo + (size_t)n0 * D_ };

    auto load_stage = [&](int buf, int kBase) {
        const uint32_t base = sb + buf * STAGE_BYTES;
#pragma unroll
        for (int j = 0; j < 6; j++) {
            const __nv_bfloat16* p = planes[j];
            const uint32_t slab = base + j * SLAB_BYTES;
#pragma unroll
            for (int i = 0; i < 4; i++) {
                const int chunk = i * 256 + tid;
                const int row = chunk >> 3;
                const int cc = chunk & 7;
                const uint32_t dst = slab + SWZ(row * 128 + cc * 16);
                const void* src = p + (size_t)row * D_ + kBase + cc * 8;
                asm volatile("cp.async.cg.shared.global [%0], [%1], 16;" :: "r"(dst), "l"(src));
            }
        }
        asm volatile("cp.async.commit_group;" ::: "memory");
    };

    float acc[4][4][4];
#pragma unroll
    for (int a = 0; a < 4; a++)
#pragma unroll
        for (int b = 0; b < 4; b++)
#pragma unroll
            for (int r = 0; r < 4; r++) acc[a][b][r] = 0.0f;

    load_stage(0, 0);
    load_stage(1, TILE_K);

    const int aRow = (lane & 15);
    const int aCh  = (lane >> 4);
    const int bRow = (lane & 7) + ((lane >> 4) << 3);
    const int bCh  = (lane >> 3) & 1;

    const int NSTAGE = D_ / TILE_K;   // 8
    for (int s = 0; s < NSTAGE; s++) {
        const int b = s & 1;
        if (s < NSTAGE - 1)
            asm volatile("cp.async.wait_group 1;" ::: "memory");
        else
            asm volatile("cp.async.wait_group 0;" ::: "memory");
        __syncthreads();

        const uint32_t stg = sb + b * STAGE_BYTES;
#pragma unroll
        for (int kk = 0; kk < 4; kk++) {
            uint32_t Bf[3][8];
#pragma unroll
            for (int pb = 0; pb < 3; pb++) {
                const uint32_t slab = stg + (3 + pb) * SLAB_BYTES;
#pragma unroll
                for (int nt2 = 0; nt2 < 2; nt2++) {
                    const int row = wn * 32 + nt2 * 16 + bRow;
                    const uint32_t ad = slab + SWZ(row * 128 + kk * 32 + bCh * 16);
                    LDSM4(&Bf[pb][nt2 * 4], ad);
                }
            }
#pragma unroll
            for (int pa = 0; pa < 3; pa++) {
                uint32_t Af[4][4];
                const uint32_t slab = stg + pa * SLAB_BYTES;
#pragma unroll
                for (int mt = 0; mt < 4; mt++) {
                    const int row = wm * 64 + mt * 16 + aRow;
                    const uint32_t ad = slab + SWZ(row * 128 + kk * 32 + aCh * 16);
                    LDSM4(Af[mt], ad);
                }
                const int nProd = 3 - pa;
#pragma unroll
                for (int pb = 0; pb < 3; pb++) {
                    if (pb >= nProd) break;
#pragma unroll
                    for (int mt = 0; mt < 4; mt++) {
#pragma unroll
                        for (int nt2 = 0; nt2 < 2; nt2++) {
                            MMA16816(acc[mt][nt2 * 2 + 0], Af[mt], &Bf[pb][nt2 * 4 + 0]);
                            MMA16816(acc[mt][nt2 * 2 + 1], Af[mt], &Bf[pb][nt2 * 4 + 2]);
                        }
                    }
                }
            }
        }
        __syncthreads();
        if (s + 2 < NSTAGE) load_stage(b, (s + 2) * TILE_K);
    }

    const int rBase = m0 + wm * 64 + (lane >> 2);
    const int cBase = n0 + wn * 32 + 2 * (lane & 3);
#pragma unroll
    for (int mt = 0; mt < 4; mt++) {
#pragma unroll
        for (int nt = 0; nt < 4; nt++) {
            const int col = cBase + nt * 8;
            const float b0 = bias[col], b1 = bias[col + 1];
            const int r0 = rBase + mt * 16;
            float2 o0 = make_float2(acc[mt][nt][0] + b0, acc[mt][nt][1] + b1);
            float2 o1 = make_float2(acc[mt][nt][2] + b0, acc[mt][nt][3] + b1);
            __stwt((float2*)&g_hall[(size_t)r0 * H_ + col], o0);
            __stwt((float2*)&g_hall[(size_t)(r0 + 8) * H_ + col], o1);
        }
    }
}

// ---------------- fast LIF scan + at-risk flagging ----------------
__global__ void __launch_bounds__(256) scan_flag_kernel()
{
    const int idx = blockIdx.x * blockDim.x + threadIdx.x;
    const int flat = idx * 4;
    const float* p = g_hall + (size_t)flat;

    float v[4] = {0.f, 0.f, 0.f, 0.f};
    float z[4] = {0.f, 0.f, 0.f, 0.f};
    float mm[4] = {1e9f, 1e9f, 1e9f, 1e9f};

#pragma unroll 4
    for (int t = 0; t < T_; t++) {
        const float4 hv = __ldcs((const float4*)(p + (size_t)t * ((size_t)B_ * H_)));
        const float hh[4] = {hv.x, hv.y, hv.z, hv.w};
#pragma unroll
        for (int j = 0; j < 4; j++) {
            v[j] = 0.9f * v[j] + hh[j];
            const float d = v[j] - 1.0f;
            mm[j] = fminf(mm[j], fabsf(d));
            z[j] = (d > 0.0f) ? 1.0f : 0.0f;
            v[j] -= z[j];
        }
    }
    *(float4*)&g_z[flat] = make_float4(z[0], z[1], z[2], z[3]);

#pragma unroll
    for (int j = 0; j < 4; j++) {
        if (mm[j] < DELTA) {
            const unsigned int li = atomicAdd(&g_cnt, 1u);
            if (li < CAP) g_list[li] = flat + j;
        }
    }
}

// ---------------- fixup: exact h for flagged neurons (round-1 arithmetic) ----------------
__global__ void __launch_bounds__(256) fixup_h_kernel(const float* __restrict__ x,
                                                      const float* __restrict__ W,
                                                      const float* __restrict__ bias)
{
    const unsigned int cnt = min(g_cnt, (unsigned int)CAP);
    const unsigned int total = cnt * T_;
    for (unsigned int i = blockIdx.x * blockDim.x + threadIdx.x; i < total;
         i += gridDim.x * blockDim.x) {
        const unsigned int li = i >> 7;         // list index
        const int t = (int)(i & 127);
        const int fl = g_list[li];
        const int b = fl / H_;
        const int h = fl % H_;
        const float* xr = x + ((size_t)t * B_ + b) * D_;
        const float* wr = W + (size_t)h * D_;
        float acc = 0.0f;
        // k-sequential fp32, increasing k (matches round-1 validated arithmetic)
#pragma unroll 4
        for (int k = 0; k < D_; k += 4) {
            const float4 xv = *(const float4*)(xr + k);
            const float4 wv = *(const float4*)(wr + k);
            acc = fmaf(xv.x, wv.x, acc);
            acc = fmaf(xv.y, wv.y, acc);
            acc = fmaf(xv.z, wv.z, acc);
            acc = fmaf(xv.w, wv.w, acc);
        }
        g_hfix[(size_t)li * T_ + t] = acc + bias[h];
    }
}

__global__ void __launch_bounds__(256) fixup_scan_kernel()
{
    const unsigned int cnt = min(g_cnt, (unsigned int)CAP);
    for (unsigned int li = blockIdx.x * blockDim.x + threadIdx.x; li < cnt;
         li += gridDim.x * blockDim.x) {
        const float* hp = g_hfix + (size_t)li * T_;
        float v = 0.0f, z = 0.0f;
#pragma unroll 4
        for (int t = 0; t < T_; t++) {
            v = 0.9f * v + hp[t];
            z = (v > 1.0f) ? 1.0f : 0.0f;
            v -= z;
        }
        g_z[g_list[li]] = z;
    }
}

// ---------------- classifier ----------------
__global__ void __launch_bounds__(256) cls_kernel(const float* __restrict__ Wout,
                                                  const float* __restrict__ bout,
                                                  float* __restrict__ out)
{
    const int gw = (blockIdx.x * blockDim.x + threadIdx.x) >> 5;
    const int lane = threadIdx.x & 31;
    if (gw >= B_ * C_) return;
    const int b = gw / C_;
    const int c = gw % C_;

    const float* zp = g_z + (size_t)b * H_;
    const float* wp = Wout + (size_t)c * H_;

    float s = 0.0f;
#pragma unroll
    for (int h = lane * 4; h < H_; h += 32 * 4) {
        const float4 zz = *(const float4*)&zp[h];
        const float4 ww = *(const float4*)&wp[h];
        s = fmaf(zz.x, ww.x, s);
        s = fmaf(zz.y, ww.y, s);
        s = fmaf(zz.z, ww.z, s);
        s = fmaf(zz.w, ww.w, s);
    }
#pragma unroll
    for (int o = 16; o > 0; o >>= 1)
        s += __shfl_xor_sync(0xffffffffu, s, o);
    if (lane == 0) out[(size_t)b * C_ + c] = s + bout[c];
}

// ---------------------------------------------------------------------------
extern "C" void kernel_launch(void* const* d_in, const int* in_sizes, int n_in,
                              void* d_out, int out_size)
{
    const float* x     = (const float*)d_in[0];  // [T, B, D]
    const float* W_in  = (const float*)d_in[1];  // [H, D]
    const float* b_in  = (const float*)d_in[2];  // [H]
    const float* W_out = (const float*)d_in[3];  // [C, H]
    const float* b_out = (const float*)d_in[4];  // [C]
    float* out = (float*)d_out;                  // [B, C]

    cudaFuncSetAttribute(gemm_hmma_kernel, cudaFuncAttributeMaxDynamicSharedMemorySize, SMEM_TOTAL);

    zero_cnt_kernel<<<1, 1>>>();
    splitA_kernel<<<(M_ * D_ / 4 + 255) / 256, 256>>>(x);
    splitB_kernel<<<(H_ * D_ / 4 + 255) / 256, 256>>>(W_in);

    dim3 g(H_ / 128, M_ / 128);                  // 16 x 512 CTAs
    gemm_hmma_kernel<<<g, 256, SMEM_TOTAL>>>(b_in);

    scan_flag_kernel<<<(B_ * H_ / 4) / 256, 256>>>();

    fixup_h_kernel<<<2048, 256>>>(x, W_in, b_in);
    fixup_scan_kernel<<<256, 256>>>();

    cls_kernel<<<(B_ * C_ * 32) / 256, 256>>>(W_out, b_out, out);
}

// round 11
// speedup vs baseline: 1.7190x; 1.7190x over previous
#include <cuda_runtime.h>
#include <cuda_bf16.h>
#include <cstdint>

#define T_ 128
#define B_ 512
#define D_ 512
#define H_ 2048
#define C_ 18
#define M_ (T_ * B_)   // 65536

#define CAP 262144           // at-risk neuron capacity (expect ~15k)
#define DELTA 2.5e-4f        // flag margin (~80 sigma of 3-product v-error)

// ---------------- device scratch (allocation-free rule) ----------------
__device__ __nv_bfloat16 g_Ahi[(size_t)M_ * D_];
__device__ __nv_bfloat16 g_Amid[(size_t)M_ * D_];
__device__ __nv_bfloat16 g_Bhi[(size_t)H_ * D_];
__device__ __nv_bfloat16 g_Bmid[(size_t)H_ * D_];
__device__ float g_hall[(size_t)M_ * H_];      // 512 MB (fast h)
__device__ float g_z[B_ * H_];
__device__ unsigned int g_cnt;
__device__ int g_list[CAP];
__device__ float g_hfix[(size_t)CAP * T_];

// ---------------- helpers ----------------
static __device__ __forceinline__ uint32_t s2u(const void* p) {
    uint32_t a;
    asm("{ .reg .u64 t; cvta.to.shared.u64 t, %1; cvt.u32.u64 %0, t; }" : "=r"(a) : "l"(p));
    return a;
}
#define SWZ(o) ((o) ^ (((o) >> 3) & 0x70))

#define LDSM4(r, a) \
    asm volatile("ldmatrix.sync.aligned.m8n8.x4.shared.b16 {%0,%1,%2,%3}, [%4];" \
                 : "=r"((r)[0]), "=r"((r)[1]), "=r"((r)[2]), "=r"((r)[3]) : "r"(a))

#define MMA16816(d, a, b) \
    asm volatile("mma.sync.aligned.m16n8k16.row.col.f32.bf16.bf16.f32 " \
                 "{%0,%1,%2,%3}, {%4,%5,%6,%7}, {%8,%9}, {%0,%1,%2,%3};" \
                 : "+f"((d)[0]), "+f"((d)[1]), "+f"((d)[2]), "+f"((d)[3]) \
                 : "r"((a)[0]), "r"((a)[1]), "r"((a)[2]), "r"((a)[3]), \
                   "r"((b)[0]), "r"((b)[1]))

// ---------------- split: fp32 -> exact 2-way bf16 (hi + mid) ----------------
static __device__ __forceinline__ uint32_t pk(__nv_bfloat16 a, __nv_bfloat16 b) {
    return (uint32_t)__bfloat16_as_ushort(a) | ((uint32_t)__bfloat16_as_ushort(b) << 16);
}

static __device__ __forceinline__ void split2(const float* __restrict__ src,
                                              __nv_bfloat16* __restrict__ hi,
                                              __nv_bfloat16* __restrict__ mid,
                                              int i)
{
    float4 v = ((const float4*)src)[i];
    float a[4] = {v.x, v.y, v.z, v.w};
    __nv_bfloat16 h[4], m[4];
#pragma unroll
    for (int j = 0; j < 4; j++) {
        float x = a[j];
        __nv_bfloat16 xh = __float2bfloat16(x);
        float r1 = x - __bfloat162float(xh);
        h[j] = xh; m[j] = __float2bfloat16(r1);
    }
    uint2 oh, om;
    oh.x = pk(h[0], h[1]); oh.y = pk(h[2], h[3]);
    om.x = pk(m[0], m[1]); om.y = pk(m[2], m[3]);
    *(uint2*)(hi  + 4 * (size_t)i) = oh;
    *(uint2*)(mid + 4 * (size_t)i) = om;
}

__global__ void __launch_bounds__(256) splitA_kernel(const float* __restrict__ src) {
    int i = blockIdx.x * blockDim.x + threadIdx.x;
    if (i < M_ * D_ / 4) split2(src, g_Ahi, g_Amid, i);
}
__global__ void __launch_bounds__(256) splitB_kernel(const float* __restrict__ src) {
    int i = blockIdx.x * blockDim.x + threadIdx.x;
    if (i < H_ * D_ / 4) split2(src, g_Bhi, g_Bmid, i);
}

__global__ void zero_cnt_kernel() { g_cnt = 0u; }

// ---------------- fast HMMA GEMM: 3 products (hh, hm, mh), 3-stage ring ----------------
#define TILE_K 64
#define SLAB_BYTES 16384                  // 128 rows x 128 B
#define STAGE_BYTES (4 * SLAB_BYTES)      // Ahi, Amid, Bhi, Bmid = 64 KB
#define SMEM_TOTAL (3 * STAGE_BYTES)      // 192 KB (3-buffer ring)

__global__ void __launch_bounds__(256, 1) gemm_hmma_kernel(const float* __restrict__ bias)
{
    extern __shared__ char smem[];
    const uint32_t sb = s2u(smem);
    const int tid = threadIdx.x;
    const int wid = tid >> 5;
    const int lane = tid & 31;
    const int wm = wid >> 2;          // 0..1
    const int wn = wid & 3;           // 0..3

    const int m0 = (int)blockIdx.y * 128;
    const int n0 = (int)blockIdx.x * 128;

    const __nv_bfloat16* planes[4] = {
        g_Ahi  + (size_t)m0 * D_, g_Amid + (size_t)m0 * D_,
        g_Bhi  + (size_t)n0 * D_, g_Bmid + (size_t)n0 * D_ };

    auto load_stage = [&](int buf, int kBase) {
        const uint32_t base = sb + buf * STAGE_BYTES;
#pragma unroll
        for (int j = 0; j < 4; j++) {
            const __nv_bfloat16* p = planes[j];
            const uint32_t slab = base + j * SLAB_BYTES;
#pragma unroll
            for (int i = 0; i < 4; i++) {
                const int chunk = i * 256 + tid;   // 0..1023 (16B chunks)
                const int row = chunk >> 3;
                const int cc = chunk & 7;
                const uint32_t dst = slab + SWZ(row * 128 + cc * 16);
                const void* src = p + (size_t)row * D_ + kBase + cc * 8;
                asm volatile("cp.async.cg.shared.global [%0], [%1], 16;" :: "r"(dst), "l"(src));
            }
        }
        asm volatile("cp.async.commit_group;" ::: "memory");
    };

    float acc[4][4][4];
#pragma unroll
    for (int a = 0; a < 4; a++)
#pragma unroll
        for (int b = 0; b < 4; b++)
#pragma unroll
            for (int r = 0; r < 4; r++) acc[a][b][r] = 0.0f;

    load_stage(0, 0);
    load_stage(1, TILE_K);

    const int aRow = (lane & 15);
    const int aCh  = (lane >> 4);
    const int bRow = (lane & 7) + ((lane >> 4) << 3);
    const int bCh  = (lane >> 3) & 1;

    const int NSTAGE = D_ / TILE_K;   // 8
    for (int s = 0; s < NSTAGE; s++) {
        if (s < NSTAGE - 1)
            asm volatile("cp.async.wait_group 1;" ::: "memory");
        else
            asm volatile("cp.async.wait_group 0;" ::: "memory");
        __syncthreads();
        // buffer (s+2)%3 == (s-1)%3 is free (all threads passed the barrier above,
        // so everyone finished consuming stage s-1)
        if (s + 2 < NSTAGE) load_stage((s + 2) % 3, (s + 2) * TILE_K);

        const uint32_t stg = sb + (uint32_t)(s % 3) * STAGE_BYTES;
#pragma unroll
        for (int kk = 0; kk < 4; kk++) {
            // B fragments: hi (pb=0), mid (pb=1)
            uint32_t Bf[2][8];
#pragma unroll
            for (int pb = 0; pb < 2; pb++) {
                const uint32_t slab = stg + (2 + pb) * SLAB_BYTES;
#pragma unroll
                for (int nt2 = 0; nt2 < 2; nt2++) {
                    const int row = wn * 32 + nt2 * 16 + bRow;
                    const uint32_t ad = slab + SWZ(row * 128 + kk * 32 + bCh * 16);
                    LDSM4(&Bf[pb][nt2 * 4], ad);
                }
            }
            // A hi: products hh + hm; A mid: product mh
#pragma unroll
            for (int pa = 0; pa < 2; pa++) {
                uint32_t Af[4][4];
                const uint32_t slab = stg + pa * SLAB_BYTES;
#pragma unroll
                for (int mt = 0; mt < 4; mt++) {
                    const int row = wm * 64 + mt * 16 + aRow;
                    const uint32_t ad = slab + SWZ(row * 128 + kk * 32 + aCh * 16);
                    LDSM4(Af[mt], ad);
                }
                const int nProd = 2 - pa;   // pa=0 -> {Bhi,Bmid}; pa=1 -> {Bhi}
#pragma unroll
                for (int pb = 0; pb < 2; pb++) {
                    if (pb >= nProd) break;
#pragma unroll
                    for (int mt = 0; mt < 4; mt++) {
#pragma unroll
                        for (int nt2 = 0; nt2 < 2; nt2++) {
                            MMA16816(acc[mt][nt2 * 2 + 0], Af[mt], &Bf[pb][nt2 * 4 + 0]);
                            MMA16816(acc[mt][nt2 * 2 + 1], Af[mt], &Bf[pb][nt2 * 4 + 2]);
                        }
                    }
                }
            }
        }
    }

    const int rBase = m0 + wm * 64 + (lane >> 2);
    const int cBase = n0 + wn * 32 + 2 * (lane & 3);
#pragma unroll
    for (int mt = 0; mt < 4; mt++) {
#pragma unroll
        for (int nt = 0; nt < 4; nt++) {
            const int col = cBase + nt * 8;
            const float b0 = bias[col], b1 = bias[col + 1];
            const int r0 = rBase + mt * 16;
            float2 o0 = make_float2(acc[mt][nt][0] + b0, acc[mt][nt][1] + b1);
            float2 o1 = make_float2(acc[mt][nt][2] + b0, acc[mt][nt][3] + b1);
            __stwt((float2*)&g_hall[(size_t)r0 * H_ + col], o0);
            __stwt((float2*)&g_hall[(size_t)(r0 + 8) * H_ + col], o1);
        }
    }
}

// ---------------- fast LIF scan + at-risk flagging ----------------
__global__ void __launch_bounds__(256) scan_flag_kernel()
{
    const int idx = blockIdx.x * blockDim.x + threadIdx.x;
    const int flat = idx * 4;
    const float* p = g_hall + (size_t)flat;

    float v[4] = {0.f, 0.f, 0.f, 0.f};
    float z[4] = {0.f, 0.f, 0.f, 0.f};
    float mm[4] = {1e9f, 1e9f, 1e9f, 1e9f};

#pragma unroll 4
    for (int t = 0; t < T_; t++) {
        const float4 hv = __ldcs((const float4*)(p + (size_t)t * ((size_t)B_ * H_)));
        const float hh[4] = {hv.x, hv.y, hv.z, hv.w};
#pragma unroll
        for (int j = 0; j < 4; j++) {
            v[j] = 0.9f * v[j] + hh[j];
            const float d = v[j] - 1.0f;
            mm[j] = fminf(mm[j], fabsf(d));
            z[j] = (d > 0.0f) ? 1.0f : 0.0f;
            v[j] -= z[j];
        }
    }
    *(float4*)&g_z[flat] = make_float4(z[0], z[1], z[2], z[3]);

#pragma unroll
    for (int j = 0; j < 4; j++) {
        if (mm[j] < DELTA) {
            const unsigned int li = atomicAdd(&g_cnt, 1u);
            if (li < CAP) g_list[li] = flat + j;
        }
    }
}

// ---------------- fixup: exact h for flagged neurons, COALESCED ----------------
// One CTA per flagged neuron (b,h). 128 threads = one per t.
// Per 64-k tile: stage x[t][k] (coalesced, pad-65 -> conflict-free) + W row,
// then each thread accumulates k-sequentially (bit-identical to round-1 path).
#define FIX_KT 64

__global__ void __launch_bounds__(128) fixup_h_kernel(const float* __restrict__ x,
                                                      const float* __restrict__ W,
                                                      const float* __restrict__ bias)
{
    __shared__ float xs[T_][FIX_KT + 1];   // 128 x 65 floats = 33.3 KB
    __shared__ float ws[FIX_KT];

    const unsigned int cnt = min(g_cnt, (unsigned int)CAP);
    const int tid = threadIdx.x;           // = t

    for (unsigned int li = blockIdx.x; li < cnt; li += gridDim.x) {
        const int fl = g_list[li];
        const int b = fl / H_;
        const int h = fl % H_;
        const float* wr = W + (size_t)h * D_;
        float acc = 0.0f;

        for (int k0 = 0; k0 < D_; k0 += FIX_KT) {
            // coalesced stage of x[t, b, k0:k0+64] for all t
#pragma unroll
            for (int i = 0; i < 16; i++) {
                const int idx = i * 128 + tid;      // 0..2047 float4 chunks
                const int row = idx >> 4;           // t
                const int c4 = idx & 15;            // float4 within row
                const float4 v = *(const float4*)(x + ((size_t)row * B_ + b) * D_ + k0 + c4 * 4);
                xs[row][c4 * 4 + 0] = v.x;
                xs[row][c4 * 4 + 1] = v.y;
                xs[row][c4 * 4 + 2] = v.z;
                xs[row][c4 * 4 + 3] = v.w;
            }
            if (tid < FIX_KT / 4) {
                const float4 wv = *(const float4*)(wr + k0 + tid * 4);
                ws[tid * 4 + 0] = wv.x;
                ws[tid * 4 + 1] = wv.y;
                ws[tid * 4 + 2] = wv.z;
                ws[tid * 4 + 3] = wv.w;
            }
            __syncthreads();
            // k-sequential accumulation (identical order/ops to validated path)
#pragma unroll
            for (int k = 0; k < FIX_KT; k++)
                acc = fmaf(xs[tid][k], ws[k], acc);
            __syncthreads();
        }
        g_hfix[(size_t)li * T_ + tid] = acc + bias[h];
    }
}

__global__ void __launch_bounds__(256) fixup_scan_kernel()
{
    const unsigned int cnt = min(g_cnt, (unsigned int)CAP);
    for (unsigned int li = blockIdx.x * blockDim.x + threadIdx.x; li < cnt;
         li += gridDim.x * blockDim.x) {
        const float* hp = g_hfix + (size_t)li * T_;
        float v = 0.0f, z = 0.0f;
#pragma unroll 4
        for (int t = 0; t < T_; t++) {
            v = 0.9f * v + hp[t];
            z = (v > 1.0f) ? 1.0f : 0.0f;
            v -= z;
        }
        g_z[g_list[li]] = z;
    }
}

// ---------------- classifier ----------------
__global__ void __launch_bounds__(256) cls_kernel(const float* __restrict__ Wout,
                                                  const float* __restrict__ bout,
                                                  float* __restrict__ out)
{
    const int gw = (blockIdx.x * blockDim.x + threadIdx.x) >> 5;
    const int lane = threadIdx.x & 31;
    if (gw >= B_ * C_) return;
    const int b = gw / C_;
    const int c = gw % C_;

    const float* zp = g_z + (size_t)b * H_;
    const float* wp = Wout + (size_t)c * H_;

    float s = 0.0f;
#pragma unroll
    for (int h = lane * 4; h < H_; h += 32 * 4) {
        const float4 zz = *(const float4*)&zp[h];
        const float4 ww = *(const float4*)&wp[h];
        s = fmaf(zz.x, ww.x, s);
        s = fmaf(zz.y, ww.y, s);
        s = fmaf(zz.z, ww.z, s);
        s = fmaf(zz.w, ww.w, s);
    }
#pragma unroll
    for (int o = 16; o > 0; o >>= 1)
        s += __shfl_xor_sync(0xffffffffu, s, o);
    if (lane == 0) out[(size_t)b * C_ + c] = s + bout[c];
}

// ---------------------------------------------------------------------------
extern "C" void kernel_launch(void* const* d_in, const int* in_sizes, int n_in,
                              void* d_out, int out_size)
{
    const float* x     = (const float*)d_in[0];  // [T, B, D]
    const float* W_in  = (const float*)d_in[1];  // [H, D]
    const float* b_in  = (const float*)d_in[2];  // [H]
    const float* W_out = (const float*)d_in[3];  // [C, H]
    const float* b_out = (const float*)d_in[4];  // [C]
    float* out = (float*)d_out;                  // [B, C]

    cudaFuncSetAttribute(gemm_hmma_kernel, cudaFuncAttributeMaxDynamicSharedMemorySize, SMEM_TOTAL);

    zero_cnt_kernel<<<1, 1>>>();
    splitA_kernel<<<(M_ * D_ / 4 + 255) / 256, 256>>>(x);
    splitB_kernel<<<(H_ * D_ / 4 + 255) / 256, 256>>>(W_in);

    dim3 g(H_ / 128, M_ / 128);                  // 16 x 512 CTAs
    gemm_hmma_kernel<<<g, 256, SMEM_TOTAL>>>(b_in);

    scan_flag_kernel<<<(B_ * H_ / 4) / 256, 256>>>();

    fixup_h_kernel<<<4096, 128>>>(x, W_in, b_in);
    fixup_scan_kernel<<<256, 256>>>();

    cls_kernel<<<(B_ * C_ * 32) / 256, 256>>>(W_out, b_out, out);
}

// round 12
// speedup vs baseline: 2.1716x; 1.2633x over previous
#include <cuda_runtime.h>
#include <cuda_bf16.h>
#include <cstdint>

#define T_ 128
#define B_ 512
#define D_ 512
#define H_ 2048
#define C_ 18
#define M_ (T_ * B_)   // 65536

#define CAP 262144           // global at-risk capacity
#define CAPB 2048            // per-batch-row capacity (expect ~30)
#define DELTA 2.5e-4f        // flag margin
#define NHG 16               // h-group size in fixup

// ---------------- device scratch (allocation-free rule) ----------------
__device__ __nv_bfloat16 g_Ahi[(size_t)M_ * D_];
__device__ __nv_bfloat16 g_Amid[(size_t)M_ * D_];
__device__ __nv_bfloat16 g_Bhi[(size_t)H_ * D_];
__device__ __nv_bfloat16 g_Bmid[(size_t)H_ * D_];
__device__ float g_hall[(size_t)M_ * H_];      // 512 MB (fast h)
__device__ float g_z[B_ * H_];
__device__ unsigned int g_cnt;
__device__ unsigned int g_bcnt[B_];
__device__ int g_list[CAP];                    // flat neuron ids
__device__ int g_blist[B_ * CAPB];             // global li per bucket
__device__ float g_hfix[(size_t)CAP * T_];

// ---------------- helpers ----------------
static __device__ __forceinline__ uint32_t s2u(const void* p) {
    uint32_t a;
    asm("{ .reg .u64 t; cvta.to.shared.u64 t, %1; cvt.u32.u64 %0, t; }" : "=r"(a) : "l"(p));
    return a;
}
#define SWZ(o) ((o) ^ (((o) >> 3) & 0x70))

#define LDSM4(r, a) \
    asm volatile("ldmatrix.sync.aligned.m8n8.x4.shared.b16 {%0,%1,%2,%3}, [%4];" \
                 : "=r"((r)[0]), "=r"((r)[1]), "=r"((r)[2]), "=r"((r)[3]) : "r"(a))

#define MMA16816(d, a, b) \
    asm volatile("mma.sync.aligned.m16n8k16.row.col.f32.bf16.bf16.f32 " \
                 "{%0,%1,%2,%3}, {%4,%5,%6,%7}, {%8,%9}, {%0,%1,%2,%3};" \
                 : "+f"((d)[0]), "+f"((d)[1]), "+f"((d)[2]), "+f"((d)[3]) \
                 : "r"((a)[0]), "r"((a)[1]), "r"((a)[2]), "r"((a)[3]), \
                   "r"((b)[0]), "r"((b)[1]))

// ---------------- split: fp32 -> exact 2-way bf16 (hi + mid) ----------------
static __device__ __forceinline__ uint32_t pk(__nv_bfloat16 a, __nv_bfloat16 b) {
    return (uint32_t)__bfloat16_as_ushort(a) | ((uint32_t)__bfloat16_as_ushort(b) << 16);
}

static __device__ __forceinline__ void split2(const float* __restrict__ src,
                                              __nv_bfloat16* __restrict__ hi,
                                              __nv_bfloat16* __restrict__ mid,
                                              int i)
{
    float4 v = ((const float4*)src)[i];
    float a[4] = {v.x, v.y, v.z, v.w};
    __nv_bfloat16 h[4], m[4];
#pragma unroll
    for (int j = 0; j < 4; j++) {
        float x = a[j];
        __nv_bfloat16 xh = __float2bfloat16(x);
        float r1 = x - __bfloat162float(xh);
        h[j] = xh; m[j] = __float2bfloat16(r1);
    }
    uint2 oh, om;
    oh.x = pk(h[0], h[1]); oh.y = pk(h[2], h[3]);
    om.x = pk(m[0], m[1]); om.y = pk(m[2], m[3]);
    *(uint2*)(hi  + 4 * (size_t)i) = oh;
    *(uint2*)(mid + 4 * (size_t)i) = om;
}

__global__ void __launch_bounds__(256) splitA_kernel(const float* __restrict__ src) {
    int i = blockIdx.x * blockDim.x + threadIdx.x;
    if (i < M_ * D_ / 4) split2(src, g_Ahi, g_Amid, i);
}
__global__ void __launch_bounds__(256) splitB_kernel(const float* __restrict__ src) {
    int i = blockIdx.x * blockDim.x + threadIdx.x;
    if (i < H_ * D_ / 4) split2(src, g_Bhi, g_Bmid, i);
}

__global__ void __launch_bounds__(512) zero_cnt_kernel() {
    if (threadIdx.x == 0) g_cnt = 0u;
    g_bcnt[threadIdx.x] = 0u;
}

// ---------------- fast HMMA GEMM: 3 products (hh, hm, mh), 3-stage ring ----------------
#define TILE_K 64
#define SLAB_BYTES 16384
#define STAGE_BYTES (4 * SLAB_BYTES)      // 64 KB
#define SMEM_TOTAL (3 * STAGE_BYTES)      // 192 KB

__global__ void __launch_bounds__(256, 1) gemm_hmma_kernel(const float* __restrict__ bias)
{
    extern __shared__ char smem[];
    const uint32_t sb = s2u(smem);
    const int tid = threadIdx.x;
    const int wid = tid >> 5;
    const int lane = tid & 31;
    const int wm = wid >> 2;
    const int wn = wid & 3;

    const int m0 = (int)blockIdx.y * 128;
    const int n0 = (int)blockIdx.x * 128;

    const __nv_bfloat16* planes[4] = {
        g_Ahi  + (size_t)m0 * D_, g_Amid + (size_t)m0 * D_,
        g_Bhi  + (size_t)n0 * D_, g_Bmid + (size_t)n0 * D_ };

    auto load_stage = [&](int buf, int kBase) {
        const uint32_t base = sb + buf * STAGE_BYTES;
#pragma unroll
        for (int j = 0; j < 4; j++) {
            const __nv_bfloat16* p = planes[j];
            const uint32_t slab = base + j * SLAB_BYTES;
#pragma unroll
            for (int i = 0; i < 4; i++) {
                const int chunk = i * 256 + tid;
                const int row = chunk >> 3;
                const int cc = chunk & 7;
                const uint32_t dst = slab + SWZ(row * 128 + cc * 16);
                const void* src = p + (size_t)row * D_ + kBase + cc * 8;
                asm volatile("cp.async.cg.shared.global [%0], [%1], 16;" :: "r"(dst), "l"(src));
            }
        }
        asm volatile("cp.async.commit_group;" ::: "memory");
    };

    float acc[4][4][4];
#pragma unroll
    for (int a = 0; a < 4; a++)
#pragma unroll
        for (int b = 0; b < 4; b++)
#pragma unroll
            for (int r = 0; r < 4; r++) acc[a][b][r] = 0.0f;

    load_stage(0, 0);
    load_stage(1, TILE_K);

    const int aRow = (lane & 15);
    const int aCh  = (lane >> 4);
    const int bRow = (lane & 7) + ((lane >> 4) << 3);
    const int bCh  = (lane >> 3) & 1;

    const int NSTAGE = D_ / TILE_K;   // 8
    for (int s = 0; s < NSTAGE; s++) {
        if (s < NSTAGE - 1)
            asm volatile("cp.async.wait_group 1;" ::: "memory");
        else
            asm volatile("cp.async.wait_group 0;" ::: "memory");
        __syncthreads();
        if (s + 2 < NSTAGE) load_stage((s + 2) % 3, (s + 2) * TILE_K);

        const uint32_t stg = sb + (uint32_t)(s % 3) * STAGE_BYTES;
#pragma unroll
        for (int kk = 0; kk < 4; kk++) {
            uint32_t Bf[2][8];
#pragma unroll
            for (int pb = 0; pb < 2; pb++) {
                const uint32_t slab = stg + (2 + pb) * SLAB_BYTES;
#pragma unroll
                for (int nt2 = 0; nt2 < 2; nt2++) {
                    const int row = wn * 32 + nt2 * 16 + bRow;
                    const uint32_t ad = slab + SWZ(row * 128 + kk * 32 + bCh * 16);
                    LDSM4(&Bf[pb][nt2 * 4], ad);
                }
            }
#pragma unroll
            for (int pa = 0; pa < 2; pa++) {
                uint32_t Af[4][4];
                const uint32_t slab = stg + pa * SLAB_BYTES;
#pragma unroll
                for (int mt = 0; mt < 4; mt++) {
                    const int row = wm * 64 + mt * 16 + aRow;
                    const uint32_t ad = slab + SWZ(row * 128 + kk * 32 + aCh * 16);
                    LDSM4(Af[mt], ad);
                }
                const int nProd = 2 - pa;
#pragma unroll
                for (int pb = 0; pb < 2; pb++) {
                    if (pb >= nProd) break;
#pragma unroll
                    for (int mt = 0; mt < 4; mt++) {
#pragma unroll
                        for (int nt2 = 0; nt2 < 2; nt2++) {
                            MMA16816(acc[mt][nt2 * 2 + 0], Af[mt], &Bf[pb][nt2 * 4 + 0]);
                            MMA16816(acc[mt][nt2 * 2 + 1], Af[mt], &Bf[pb][nt2 * 4 + 2]);
                        }
                    }
                }
            }
        }
    }

    const int rBase = m0 + wm * 64 + (lane >> 2);
    const int cBase = n0 + wn * 32 + 2 * (lane & 3);
#pragma unroll
    for (int mt = 0; mt < 4; mt++) {
#pragma unroll
        for (int nt = 0; nt < 4; nt++) {
            const int col = cBase + nt * 8;
            const float b0 = bias[col], b1 = bias[col + 1];
            const int r0 = rBase + mt * 16;
            float2 o0 = make_float2(acc[mt][nt][0] + b0, acc[mt][nt][1] + b1);
            float2 o1 = make_float2(acc[mt][nt][2] + b0, acc[mt][nt][3] + b1);
            __stwt((float2*)&g_hall[(size_t)r0 * H_ + col], o0);
            __stwt((float2*)&g_hall[(size_t)(r0 + 8) * H_ + col], o1);
        }
    }
}

// ---------------- fast LIF scan + at-risk flagging (bucketed) ----------------
__global__ void __launch_bounds__(256) scan_flag_kernel()
{
    const int idx = blockIdx.x * blockDim.x + threadIdx.x;
    const int flat = idx * 4;
    const float* p = g_hall + (size_t)flat;

    float v[4] = {0.f, 0.f, 0.f, 0.f};
    float z[4] = {0.f, 0.f, 0.f, 0.f};
    float mm[4] = {1e9f, 1e9f, 1e9f, 1e9f};

#pragma unroll 4
    for (int t = 0; t < T_; t++) {
        const float4 hv = __ldcs((const float4*)(p + (size_t)t * ((size_t)B_ * H_)));
        const float hh[4] = {hv.x, hv.y, hv.z, hv.w};
#pragma unroll
        for (int j = 0; j < 4; j++) {
            v[j] = 0.9f * v[j] + hh[j];
            const float d = v[j] - 1.0f;
            mm[j] = fminf(mm[j], fabsf(d));
            z[j] = (d > 0.0f) ? 1.0f : 0.0f;
            v[j] -= z[j];
        }
    }
    *(float4*)&g_z[flat] = make_float4(z[0], z[1], z[2], z[3]);

    const int b = flat / H_;   // same b for all 4 lanes of this float4
#pragma unroll
    for (int j = 0; j < 4; j++) {
        if (mm[j] < DELTA) {
            const unsigned int li = atomicAdd(&g_cnt, 1u);
            if (li < CAP) {
                g_list[li] = flat + j;
                const unsigned int p2 = atomicAdd(&g_bcnt[b], 1u);
                if (p2 < CAPB) g_blist[b * CAPB + p2] = (int)li;
            }
        }
    }
}

// ---------------- fixup: exact h, bucketed by b (x tile staged once/group) ----------------
#define FIX_KT 64

__global__ void __launch_bounds__(128) fixup_h_kernel(const float* __restrict__ x,
                                                      const float* __restrict__ W,
                                                      const float* __restrict__ bias)
{
    __shared__ float xs[T_][FIX_KT + 1];     // 33 KB
    __shared__ float ws[NHG][FIX_KT + 1];    // 4.1 KB
    __shared__ int hsm[NHG];
    __shared__ int lim[NHG];

    const int b = blockIdx.x;                // 512 CTAs, one per batch row
    const unsigned int cnt = min(g_bcnt[b], (unsigned int)CAPB);
    const int tid = threadIdx.x;             // = t

    for (unsigned int g = 0; g < cnt; g += NHG) {
        const int nh = (int)min((unsigned int)NHG, cnt - g);

        if (tid < nh) {
            const int li = g_blist[b * CAPB + g + tid];
            lim[tid] = li;
            hsm[tid] = g_list[li] % H_;
        }
        __syncthreads();

        float acc[NHG];
#pragma unroll
        for (int j = 0; j < NHG; j++) acc[j] = 0.0f;

        for (int kt = 0; kt < D_ / FIX_KT; kt++) {   // 8 k-tiles, ascending
            const int k0 = kt * FIX_KT;
            // stage x[t, b, k0:k0+64] for all t (fully coalesced)
#pragma unroll
            for (int i = 0; i < 16; i++) {
                const int idx = i * 128 + tid;       // 0..2047 float4 chunks
                const int row = idx >> 4;            // t
                const int c4 = idx & 15;
                const float4 v = *(const float4*)(x + ((size_t)row * B_ + b) * D_ + k0 + c4 * 4);
                xs[row][c4 * 4 + 0] = v.x;
                xs[row][c4 * 4 + 1] = v.y;
                xs[row][c4 * 4 + 2] = v.z;
                xs[row][c4 * 4 + 3] = v.w;
            }
            // stage W rows for this h-group (nh x 64 floats = up to 256 float4)
#pragma unroll
            for (int i = 0; i < 2; i++) {
                const int idx = i * 128 + tid;       // 0..255
                const int j = idx >> 4;
                const int c4 = idx & 15;
                if (j < nh) {
                    const float4 wv = *(const float4*)(W + (size_t)hsm[j] * D_ + k0 + c4 * 4);
                    ws[j][c4 * 4 + 0] = wv.x;
                    ws[j][c4 * 4 + 1] = wv.y;
                    ws[j][c4 * 4 + 2] = wv.z;
                    ws[j][c4 * 4 + 3] = wv.w;
                }
            }
            __syncthreads();
            // k-sequential per (j): kt outer asc, k inner asc == validated order
            if (nh == NHG) {
#pragma unroll 8
                for (int k = 0; k < FIX_KT; k++) {
                    const float xr = xs[tid][k];
#pragma unroll
                    for (int j = 0; j < NHG; j++)
                        acc[j] = fmaf(xr, ws[j][k], acc[j]);
                }
            } else {
#pragma unroll 8
                for (int k = 0; k < FIX_KT; k++) {
                    const float xr = xs[tid][k];
                    for (int j = 0; j < nh; j++)
                        acc[j] = fmaf(xr, ws[j][k], acc[j]);
                }
            }
            __syncthreads();
        }

        for (int j = 0; j < nh; j++)
            g_hfix[(size_t)lim[j] * T_ + tid] = acc[j] + bias[hsm[j]];
        __syncthreads();
    }
}

__global__ void __launch_bounds__(256) fixup_scan_kernel()
{
    const unsigned int cnt = min(g_cnt, (unsigned int)CAP);
    for (unsigned int li = blockIdx.x * blockDim.x + threadIdx.x; li < cnt;
         li += gridDim.x * blockDim.x) {
        const float* hp = g_hfix + (size_t)li * T_;
        float v = 0.0f, z = 0.0f;
#pragma unroll 4
        for (int t = 0; t < T_; t++) {
            v = 0.9f * v + hp[t];
            z = (v > 1.0f) ? 1.0f : 0.0f;
            v -= z;
        }
        g_z[g_list[li]] = z;
    }
}

// ---------------- classifier ----------------
__global__ void __launch_bounds__(256) cls_kernel(const float* __restrict__ Wout,
                                                  const float* __restrict__ bout,
                                                  float* __restrict__ out)
{
    const int gw = (blockIdx.x * blockDim.x + threadIdx.x) >> 5;
    const int lane = threadIdx.x & 31;
    if (gw >= B_ * C_) return;
    const int b = gw / C_;
    const int c = gw % C_;

    const float* zp = g_z + (size_t)b * H_;
    const float* wp = Wout + (size_t)c * H_;

    float s = 0.0f;
#pragma unroll
    for (int h = lane * 4; h < H_; h += 32 * 4) {
        const float4 zz = *(const float4*)&zp[h];
        const float4 ww = *(const float4*)&wp[h];
        s = fmaf(zz.x, ww.x, s);
        s = fmaf(zz.y, ww.y, s);
        s = fmaf(zz.z, ww.z, s);
        s = fmaf(zz.w, ww.w, s);
    }
#pragma unroll
    for (int o = 16; o > 0; o >>= 1)
        s += __shfl_xor_sync(0xffffffffu, s, o);
    if (lane == 0) out[(size_t)b * C_ + c] = s + bout[c];
}

// ---------------------------------------------------------------------------
extern "C" void kernel_launch(void* const* d_in, const int* in_sizes, int n_in,
                              void* d_out, int out_size)
{
    const float* x     = (const float*)d_in[0];  // [T, B, D]
    const float* W_in  = (const float*)d_in[1];  // [H, D]
    const float* b_in  = (const float*)d_in[2];  // [H]
    const float* W_out = (const float*)d_in[3];  // [C, H]
    const float* b_out = (const float*)d_in[4];  // [C]
    float* out = (float*)d_out;                  // [B, C]

    cudaFuncSetAttribute(gemm_hmma_kernel, cudaFuncAttributeMaxDynamicSharedMemorySize, SMEM_TOTAL);

    zero_cnt_kernel<<<1, 512>>>();
    splitA_kernel<<<(M_ * D_ / 4 + 255) / 256, 256>>>(x);
    splitB_kernel<<<(H_ * D_ / 4 + 255) / 256, 256>>>(W_in);

    dim3 g(H_ / 128, M_ / 128);                  // 16 x 512 CTAs
    gemm_hmma_kernel<<<g, 256, SMEM_TOTAL>>>(b_in);

    scan_flag_kernel<<<(B_ * H_ / 4) / 256, 256>>>();

    fixup_h_kernel<<<B_, 128>>>(x, W_in, b_in);
    fixup_scan_kernel<<<256, 256>>>();

    cls_kernel<<<(B_ * C_ * 32) / 256, 256>>>(W_out, b_out, out);
}

// round 13
// speedup vs baseline: 2.3700x; 1.0914x over previous
#include <cuda_runtime.h>
#include <cuda_bf16.h>
#include <cstdint>

#define T_ 128
#define B_ 512
#define D_ 512
#define H_ 2048
#define C_ 18
#define M_ (T_ * B_)   // 65536

#define CAPB 2048            // per-batch-row capacity (expect ~40)
#define DELTA 2.5e-4f        // flag margin
#define NHG 16               // h-group size in fixup

// ---------------- device scratch (allocation-free rule) ----------------
__device__ __nv_bfloat16 g_Ahi[(size_t)M_ * D_];
__device__ __nv_bfloat16 g_Amid[(size_t)M_ * D_];
__device__ __nv_bfloat16 g_Bhi[(size_t)H_ * D_];
__device__ __nv_bfloat16 g_Bmid[(size_t)H_ * D_];
__device__ float g_hall[(size_t)M_ * H_];      // 512 MB (fast h)
__device__ float g_z[B_ * H_];
__device__ unsigned int g_bcnt[B_];
__device__ int g_blist[B_ * CAPB];             // flat neuron ids per bucket

// ---------------- helpers ----------------
static __device__ __forceinline__ uint32_t s2u(const void* p) {
    uint32_t a;
    asm("{ .reg .u64 t; cvta.to.shared.u64 t, %1; cvt.u32.u64 %0, t; }" : "=r"(a) : "l"(p));
    return a;
}
#define SWZ(o) ((o) ^ (((o) >> 3) & 0x70))

#define LDSM4(r, a) \
    asm volatile("ldmatrix.sync.aligned.m8n8.x4.shared.b16 {%0,%1,%2,%3}, [%4];" \
                 : "=r"((r)[0]), "=r"((r)[1]), "=r"((r)[2]), "=r"((r)[3]) : "r"(a))

#define MMA16816(d, a, b) \
    asm volatile("mma.sync.aligned.m16n8k16.row.col.f32.bf16.bf16.f32 " \
                 "{%0,%1,%2,%3}, {%4,%5,%6,%7}, {%8,%9}, {%0,%1,%2,%3};" \
                 : "+f"((d)[0]), "+f"((d)[1]), "+f"((d)[2]), "+f"((d)[3]) \
                 : "r"((a)[0]), "r"((a)[1]), "r"((a)[2]), "r"((a)[3]), \
                   "r"((b)[0]), "r"((b)[1]))

// ---------------- split: fp32 -> exact 2-way bf16 (hi + mid) ----------------
static __device__ __forceinline__ uint32_t pk(__nv_bfloat16 a, __nv_bfloat16 b) {
    return (uint32_t)__bfloat16_as_ushort(a) | ((uint32_t)__bfloat16_as_ushort(b) << 16);
}

static __device__ __forceinline__ void split2(const float* __restrict__ src,
                                              __nv_bfloat16* __restrict__ hi,
                                              __nv_bfloat16* __restrict__ mid,
                                              int i)
{
    float4 v = ((const float4*)src)[i];
    float a[4] = {v.x, v.y, v.z, v.w};
    __nv_bfloat16 h[4], m[4];
#pragma unroll
    for (int j = 0; j < 4; j++) {
        float x = a[j];
        __nv_bfloat16 xh = __float2bfloat16(x);
        float r1 = x - __bfloat162float(xh);
        h[j] = xh; m[j] = __float2bfloat16(r1);
    }
    uint2 oh, om;
    oh.x = pk(h[0], h[1]); oh.y = pk(h[2], h[3]);
    om.x = pk(m[0], m[1]); om.y = pk(m[2], m[3]);
    *(uint2*)(hi  + 4 * (size_t)i) = oh;
    *(uint2*)(mid + 4 * (size_t)i) = om;
}

__global__ void __launch_bounds__(256) splitA_kernel(const float* __restrict__ src) {
    int i = blockIdx.x * blockDim.x + threadIdx.x;
    if (i < M_ * D_ / 4) split2(src, g_Ahi, g_Amid, i);
}
__global__ void __launch_bounds__(256) splitB_kernel(const float* __restrict__ src) {
    int i = blockIdx.x * blockDim.x + threadIdx.x;
    if (i < H_ * D_ / 4) split2(src, g_Bhi, g_Bmid, i);
}

__global__ void __launch_bounds__(512) zero_cnt_kernel() {
    g_bcnt[threadIdx.x] = 0u;
}

// ---------------- fast HMMA GEMM: 3 products (hh, hm, mh), 3-stage ring ----------------
#define TILE_K 64
#define SLAB_BYTES 16384
#define STAGE_BYTES (4 * SLAB_BYTES)      // 64 KB
#define SMEM_TOTAL (3 * STAGE_BYTES)      // 192 KB

__global__ void __launch_bounds__(256, 1) gemm_hmma_kernel(const float* __restrict__ bias)
{
    extern __shared__ char smem[];
    const uint32_t sb = s2u(smem);
    const int tid = threadIdx.x;
    const int wid = tid >> 5;
    const int lane = tid & 31;
    const int wm = wid >> 2;
    const int wn = wid & 3;

    const int m0 = (int)blockIdx.y * 128;
    const int n0 = (int)blockIdx.x * 128;

    const __nv_bfloat16* planes[4] = {
        g_Ahi  + (size_t)m0 * D_, g_Amid + (size_t)m0 * D_,
        g_Bhi  + (size_t)n0 * D_, g_Bmid + (size_t)n0 * D_ };

    auto load_stage = [&](int buf, int kBase) {
        const uint32_t base = sb + buf * STAGE_BYTES;
#pragma unroll
        for (int j = 0; j < 4; j++) {
            const __nv_bfloat16* p = planes[j];
            const uint32_t slab = base + j * SLAB_BYTES;
#pragma unroll
            for (int i = 0; i < 4; i++) {
                const int chunk = i * 256 + tid;
                const int row = chunk >> 3;
                const int cc = chunk & 7;
                const uint32_t dst = slab + SWZ(row * 128 + cc * 16);
                const void* src = p + (size_t)row * D_ + kBase + cc * 8;
                asm volatile("cp.async.cg.shared.global [%0], [%1], 16;" :: "r"(dst), "l"(src));
            }
        }
        asm volatile("cp.async.commit_group;" ::: "memory");
    };

    float acc[4][4][4];
#pragma unroll
    for (int a = 0; a < 4; a++)
#pragma unroll
        for (int b = 0; b < 4; b++)
#pragma unroll
            for (int r = 0; r < 4; r++) acc[a][b][r] = 0.0f;

    load_stage(0, 0);
    load_stage(1, TILE_K);

    const int aRow = (lane & 15);
    const int aCh  = (lane >> 4);
    const int bRow = (lane & 7) + ((lane >> 4) << 3);
    const int bCh  = (lane >> 3) & 1;

    const int NSTAGE = D_ / TILE_K;   // 8
    for (int s = 0; s < NSTAGE; s++) {
        if (s < NSTAGE - 1)
            asm volatile("cp.async.wait_group 1;" ::: "memory");
        else
            asm volatile("cp.async.wait_group 0;" ::: "memory");
        __syncthreads();
        if (s + 2 < NSTAGE) load_stage((s + 2) % 3, (s + 2) * TILE_K);

        const uint32_t stg = sb + (uint32_t)(s % 3) * STAGE_BYTES;
#pragma unroll
        for (int kk = 0; kk < 4; kk++) {
            uint32_t Bf[2][8];
#pragma unroll
            for (int pb = 0; pb < 2; pb++) {
                const uint32_t slab = stg + (2 + pb) * SLAB_BYTES;
#pragma unroll
                for (int nt2 = 0; nt2 < 2; nt2++) {
                    const int row = wn * 32 + nt2 * 16 + bRow;
                    const uint32_t ad = slab + SWZ(row * 128 + kk * 32 + bCh * 16);
                    LDSM4(&Bf[pb][nt2 * 4], ad);
                }
            }
#pragma unroll
            for (int pa = 0; pa < 2; pa++) {
                uint32_t Af[4][4];
                const uint32_t slab = stg + pa * SLAB_BYTES;
#pragma unroll
                for (int mt = 0; mt < 4; mt++) {
                    const int row = wm * 64 + mt * 16 + aRow;
                    const uint32_t ad = slab + SWZ(row * 128 + kk * 32 + aCh * 16);
                    LDSM4(Af[mt], ad);
                }
                const int nProd = 2 - pa;
#pragma unroll
                for (int pb = 0; pb < 2; pb++) {
                    if (pb >= nProd) break;
#pragma unroll
                    for (int mt = 0; mt < 4; mt++) {
#pragma unroll
                        for (int nt2 = 0; nt2 < 2; nt2++) {
                            MMA16816(acc[mt][nt2 * 2 + 0], Af[mt], &Bf[pb][nt2 * 4 + 0]);
                            MMA16816(acc[mt][nt2 * 2 + 1], Af[mt], &Bf[pb][nt2 * 4 + 2]);
                        }
                    }
                }
            }
        }
    }

    const int rBase = m0 + wm * 64 + (lane >> 2);
    const int cBase = n0 + wn * 32 + 2 * (lane & 3);
#pragma unroll
    for (int mt = 0; mt < 4; mt++) {
#pragma unroll
        for (int nt = 0; nt < 4; nt++) {
            const int col = cBase + nt * 8;
            const float b0 = bias[col], b1 = bias[col + 1];
            const int r0 = rBase + mt * 16;
            float2 o0 = make_float2(acc[mt][nt][0] + b0, acc[mt][nt][1] + b1);
            float2 o1 = make_float2(acc[mt][nt][2] + b0, acc[mt][nt][3] + b1);
            __stwt((float2*)&g_hall[(size_t)r0 * H_ + col], o0);
            __stwt((float2*)&g_hall[(size_t)(r0 + 8) * H_ + col], o1);
        }
    }
}

// ---------------- fast LIF scan + at-risk flagging (bucketed, flat ids) ----------------
__global__ void __launch_bounds__(256) scan_flag_kernel()
{
    const int idx = blockIdx.x * blockDim.x + threadIdx.x;
    const int flat = idx * 4;
    const float* p = g_hall + (size_t)flat;

    float v[4] = {0.f, 0.f, 0.f, 0.f};
    float z[4] = {0.f, 0.f, 0.f, 0.f};
    float mm[4] = {1e9f, 1e9f, 1e9f, 1e9f};

#pragma unroll 4
    for (int t = 0; t < T_; t++) {
        const float4 hv = __ldcs((const float4*)(p + (size_t)t * ((size_t)B_ * H_)));
        const float hh[4] = {hv.x, hv.y, hv.z, hv.w};
#pragma unroll
        for (int j = 0; j < 4; j++) {
            v[j] = 0.9f * v[j] + hh[j];
            const float d = v[j] - 1.0f;
            mm[j] = fminf(mm[j], fabsf(d));
            z[j] = (d > 0.0f) ? 1.0f : 0.0f;
            v[j] -= z[j];
        }
    }
    *(float4*)&g_z[flat] = make_float4(z[0], z[1], z[2], z[3]);

    const int b = flat / H_;
#pragma unroll
    for (int j = 0; j < 4; j++) {
        if (mm[j] < DELTA) {
            const unsigned int p2 = atomicAdd(&g_bcnt[b], 1u);
            if (p2 < CAPB) g_blist[b * CAPB + p2] = flat + j;
        }
    }
}

// ---------------- fixup: exact h + scan, register-tiled (4t x 4j) ----------------
// One CTA per batch row. smem: xs[k][t] (pad 132), ws[k][j] (pad 20), hb[j][t].
// Per k: 2 x LDS.128 + 16 FMA. k-order per (t,j): ktile asc, k asc = validated order.
#define FIX_KT 64

__global__ void __launch_bounds__(128) fixup_kernel(const float* __restrict__ x,
                                                    const float* __restrict__ W,
                                                    const float* __restrict__ bias)
{
    __shared__ float xs[FIX_KT][132];   // 33792 B
    __shared__ float ws[FIX_KT][20];    // 5120 B
    __shared__ float hb[NHG][132];      // 8448 B
    __shared__ int hsm[NHG];
    __shared__ int fsm[NHG];

    const int b = blockIdx.x;
    const unsigned int cnt = min(g_bcnt[b], (unsigned int)CAPB);
    const int tid = threadIdx.x;
    const int jg = tid & 3;
    const int tg = tid >> 2;
    const int t0 = tg * 4;              // 0..124
    const int j0 = jg * 4;              // 0..12

    for (unsigned int g = 0; g < cnt; g += NHG) {
        const int nh = (int)min((unsigned int)NHG, cnt - g);
        if (tid < NHG) {
            const int fl = (tid < nh) ? g_blist[b * CAPB + g + tid] : -1;
            fsm[tid] = fl;
            hsm[tid] = (fl >= 0) ? (fl % H_) : 0;
        }
        __syncthreads();

        float acc[4][4];
#pragma unroll
        for (int i = 0; i < 4; i++)
#pragma unroll
            for (int j = 0; j < 4; j++) acc[i][j] = 0.0f;

        for (int kt = 0; kt < D_ / FIX_KT; kt++) {      // 8 k-tiles, ascending
            const int k0 = kt * FIX_KT;
            // stage xs[k][t] — k-major lanes (coalesced 128B per warp), scalar STS
            {
                const int kk = tid & 63;                // k within tile
                const int tt = tid >> 6;                // 0..1
#pragma unroll
                for (int i = 0; i < 64; i++) {
                    const int t = i * 2 + tt;
                    xs[kk][t] = x[((size_t)t * B_ + b) * D_ + k0 + kk];
                }
            }
            // stage ws[k][j] (zeros for j >= nh)
            {
#pragma unroll
                for (int i = 0; i < 8; i++) {
                    const int idx = i * 128 + tid;      // 0..1023
                    const int j = idx >> 6;
                    const int kk = idx & 63;
                    ws[kk][j] = (j < nh) ? W[(size_t)hsm[j] * D_ + k0 + kk] : 0.0f;
                }
            }
            __syncthreads();
#pragma unroll
            for (int k = 0; k < FIX_KT; k++) {
                const float4 xv = *(const float4*)&xs[k][t0];
                const float4 wv = *(const float4*)&ws[k][j0];
                const float xa[4] = {xv.x, xv.y, xv.z, xv.w};
                const float wa[4] = {wv.x, wv.y, wv.z, wv.w};
#pragma unroll
                for (int i = 0; i < 4; i++)
#pragma unroll
                    for (int j = 0; j < 4; j++)
                        acc[i][j] = fmaf(xa[i], wa[j], acc[i][j]);
            }
            __syncthreads();
        }

        // h = acc + bias -> hb[j][t]
#pragma unroll
        for (int j = 0; j < 4; j++) {
            const float bv = bias[hsm[j0 + j]];
            float4 o;
            o.x = acc[0][j] + bv; o.y = acc[1][j] + bv;
            o.z = acc[2][j] + bv; o.w = acc[3][j] + bv;
            *(float4*)&hb[j0 + j][t0] = o;
        }
        __syncthreads();

        // scan the group's neurons (threads 0..nh-1)
        if (tid < nh) {
            const float* hp = hb[tid];
            float v = 0.0f, z = 0.0f;
#pragma unroll 4
            for (int t = 0; t < T_; t++) {
                v = 0.9f * v + hp[t];
                z = (v > 1.0f) ? 1.0f : 0.0f;
                v -= z;
            }
            g_z[fsm[tid]] = z;
        }
        __syncthreads();
    }
}

// ---------------- classifier ----------------
__global__ void __launch_bounds__(256) cls_kernel(const float* __restrict__ Wout,
                                                  const float* __restrict__ bout,
                                                  float* __restrict__ out)
{
    const int gw = (blockIdx.x * blockDim.x + threadIdx.x) >> 5;
    const int lane = threadIdx.x & 31;
    if (gw >= B_ * C_) return;
    const int b = gw / C_;
    const int c = gw % C_;

    const float* zp = g_z + (size_t)b * H_;
    const float* wp = Wout + (size_t)c * H_;

    float s = 0.0f;
#pragma unroll
    for (int h = lane * 4; h < H_; h += 32 * 4) {
        const float4 zz = *(const float4*)&zp[h];
        const float4 ww = *(const float4*)&wp[h];
        s = fmaf(zz.x, ww.x, s);
        s = fmaf(zz.y, ww.y, s);
        s = fmaf(zz.z, ww.z, s);
        s = fmaf(zz.w, ww.w, s);
    }
#pragma unroll
    for (int o = 16; o > 0; o >>= 1)
        s += __shfl_xor_sync(0xffffffffu, s, o);
    if (lane == 0) out[(size_t)b * C_ + c] = s + bout[c];
}

// ---------------------------------------------------------------------------
extern "C" void kernel_launch(void* const* d_in, const int* in_sizes, int n_in,
                              void* d_out, int out_size)
{
    const float* x     = (const float*)d_in[0];  // [T, B, D]
    const float* W_in  = (const float*)d_in[1];  // [H, D]
    const float* b_in  = (const float*)d_in[2];  // [H]
    const float* W_out = (const float*)d_in[3];  // [C, H]
    const float* b_out = (const float*)d_in[4];  // [C]
    float* out = (float*)d_out;                  // [B, C]

    cudaFuncSetAttribute(gemm_hmma_kernel, cudaFuncAttributeMaxDynamicSharedMemorySize, SMEM_TOTAL);

    zero_cnt_kernel<<<1, 512>>>();
    splitA_kernel<<<(M_ * D_ / 4 + 255) / 256, 256>>>(x);
    splitB_kernel<<<(H_ * D_ / 4 + 255) / 256, 256>>>(W_in);

    dim3 g(H_ / 128, M_ / 128);                  // 16 x 512 CTAs
    gemm_hmma_kernel<<<g, 256, SMEM_TOTAL>>>(b_in);

    scan_flag_kernel<<<(B_ * H_ / 4) / 256, 256>>>();

    fixup_kernel<<<B_, 128>>>(x, W_in, b_in);

    cls_kernel<<<(B_ * C_ * 32) / 256, 256>>>(W_out, b_out, out);
}

// round 14
// speedup vs baseline: 2.3711x; 1.0004x over previous
#include <cuda_runtime.h>
#include <cuda_bf16.h>
#include <cstdint>

#define T_ 128
#define B_ 512
#define D_ 512
#define H_ 2048
#define C_ 18
#define M_ (T_ * B_)   // 65536

#define CAPB 2048            // per-batch-row capacity (expect ~40)
#define DELTA 2.5e-4f        // flag margin
#define NHG 32               // h-group size in fixup

// ---------------- device scratch (allocation-free rule) ----------------
__device__ __nv_bfloat16 g_Ahi[(size_t)M_ * D_];
__device__ __nv_bfloat16 g_Amid[(size_t)M_ * D_];
__device__ __nv_bfloat16 g_Bhi[(size_t)H_ * D_];
__device__ __nv_bfloat16 g_Bmid[(size_t)H_ * D_];
__device__ float g_hall[(size_t)M_ * H_];      // 512 MB (fast h)
__device__ float g_z[B_ * H_];
__device__ unsigned int g_bcnt[B_];
__device__ int g_blist[B_ * CAPB];             // flat neuron ids per bucket

// ---------------- helpers ----------------
static __device__ __forceinline__ uint32_t s2u(const void* p) {
    uint32_t a;
    asm("{ .reg .u64 t; cvta.to.shared.u64 t, %1; cvt.u32.u64 %0, t; }" : "=r"(a) : "l"(p));
    return a;
}
#define SWZ(o) ((o) ^ (((o) >> 3) & 0x70))

#define LDSM4(r, a) \
    asm volatile("ldmatrix.sync.aligned.m8n8.x4.shared.b16 {%0,%1,%2,%3}, [%4];" \
                 : "=r"((r)[0]), "=r"((r)[1]), "=r"((r)[2]), "=r"((r)[3]) : "r"(a))

#define MMA16816(d, a, b) \
    asm volatile("mma.sync.aligned.m16n8k16.row.col.f32.bf16.bf16.f32 " \
                 "{%0,%1,%2,%3}, {%4,%5,%6,%7}, {%8,%9}, {%0,%1,%2,%3};" \
                 : "+f"((d)[0]), "+f"((d)[1]), "+f"((d)[2]), "+f"((d)[3]) \
                 : "r"((a)[0]), "r"((a)[1]), "r"((a)[2]), "r"((a)[3]), \
                   "r"((b)[0]), "r"((b)[1]))

// ---------------- split: fp32 -> exact 2-way bf16 (hi + mid) ----------------
static __device__ __forceinline__ uint32_t pk(__nv_bfloat16 a, __nv_bfloat16 b) {
    return (uint32_t)__bfloat16_as_ushort(a) | ((uint32_t)__bfloat16_as_ushort(b) << 16);
}

static __device__ __forceinline__ void split2(const float* __restrict__ src,
                                              __nv_bfloat16* __restrict__ hi,
                                              __nv_bfloat16* __restrict__ mid,
                                              int i)
{
    float4 v = ((const float4*)src)[i];
    float a[4] = {v.x, v.y, v.z, v.w};
    __nv_bfloat16 h[4], m[4];
#pragma unroll
    for (int j = 0; j < 4; j++) {
        float x = a[j];
        __nv_bfloat16 xh = __float2bfloat16(x);
        float r1 = x - __bfloat162float(xh);
        h[j] = xh; m[j] = __float2bfloat16(r1);
    }
    uint2 oh, om;
    oh.x = pk(h[0], h[1]); oh.y = pk(h[2], h[3]);
    om.x = pk(m[0], m[1]); om.y = pk(m[2], m[3]);
    *(uint2*)(hi  + 4 * (size_t)i) = oh;
    *(uint2*)(mid + 4 * (size_t)i) = om;
}

__global__ void __launch_bounds__(256) splitA_kernel(const float* __restrict__ src) {
    int i = blockIdx.x * blockDim.x + threadIdx.x;
    if (i < M_ * D_ / 4) split2(src, g_Ahi, g_Amid, i);
}
__global__ void __launch_bounds__(256) splitB_kernel(const float* __restrict__ src) {
    int i = blockIdx.x * blockDim.x + threadIdx.x;
    if (i < H_ * D_ / 4) split2(src, g_Bhi, g_Bmid, i);
}

__global__ void __launch_bounds__(512) zero_cnt_kernel() {
    g_bcnt[threadIdx.x] = 0u;
}

// ---------------- fast HMMA GEMM: 3 products (hh, hm, mh), 3-stage ring ----------------
#define TILE_K 64
#define SLAB_BYTES 16384
#define STAGE_BYTES (4 * SLAB_BYTES)      // 64 KB
#define SMEM_TOTAL (3 * STAGE_BYTES)      // 192 KB

__global__ void __launch_bounds__(256, 1) gemm_hmma_kernel(const float* __restrict__ bias)
{
    extern __shared__ char smem[];
    const uint32_t sb = s2u(smem);
    const int tid = threadIdx.x;
    const int wid = tid >> 5;
    const int lane = tid & 31;
    const int wm = wid >> 2;
    const int wn = wid & 3;

    const int m0 = (int)blockIdx.y * 128;
    const int n0 = (int)blockIdx.x * 128;

    const __nv_bfloat16* planes[4] = {
        g_Ahi  + (size_t)m0 * D_, g_Amid + (size_t)m0 * D_,
        g_Bhi  + (size_t)n0 * D_, g_Bmid + (size_t)n0 * D_ };

    auto load_stage = [&](int buf, int kBase) {
        const uint32_t base = sb + buf * STAGE_BYTES;
#pragma unroll
        for (int j = 0; j < 4; j++) {
            const __nv_bfloat16* p = planes[j];
            const uint32_t slab = base + j * SLAB_BYTES;
#pragma unroll
            for (int i = 0; i < 4; i++) {
                const int chunk = i * 256 + tid;
                const int row = chunk >> 3;
                const int cc = chunk & 7;
                const uint32_t dst = slab + SWZ(row * 128 + cc * 16);
                const void* src = p + (size_t)row * D_ + kBase + cc * 8;
                asm volatile("cp.async.cg.shared.global [%0], [%1], 16;" :: "r"(dst), "l"(src));
            }
        }
        asm volatile("cp.async.commit_group;" ::: "memory");
    };

    float acc[4][4][4];
#pragma unroll
    for (int a = 0; a < 4; a++)
#pragma unroll
        for (int b = 0; b < 4; b++)
#pragma unroll
            for (int r = 0; r < 4; r++) acc[a][b][r] = 0.0f;

    load_stage(0, 0);
    load_stage(1, TILE_K);

    const int aRow = (lane & 15);
    const int aCh  = (lane >> 4);
    const int bRow = (lane & 7) + ((lane >> 4) << 3);
    const int bCh  = (lane >> 3) & 1;

    const int NSTAGE = D_ / TILE_K;   // 8
    for (int s = 0; s < NSTAGE; s++) {
        if (s < NSTAGE - 1)
            asm volatile("cp.async.wait_group 1;" ::: "memory");
        else
            asm volatile("cp.async.wait_group 0;" ::: "memory");
        __syncthreads();
        if (s + 2 < NSTAGE) load_stage((s + 2) % 3, (s + 2) * TILE_K);

        const uint32_t stg = sb + (uint32_t)(s % 3) * STAGE_BYTES;
#pragma unroll
        for (int kk = 0; kk < 4; kk++) {
            uint32_t Bf[2][8];
#pragma unroll
            for (int pb = 0; pb < 2; pb++) {
                const uint32_t slab = stg + (2 + pb) * SLAB_BYTES;
#pragma unroll
                for (int nt2 = 0; nt2 < 2; nt2++) {
                    const int row = wn * 32 + nt2 * 16 + bRow;
                    const uint32_t ad = slab + SWZ(row * 128 + kk * 32 + bCh * 16);
                    LDSM4(&Bf[pb][nt2 * 4], ad);
                }
            }
#pragma unroll
            for (int pa = 0; pa < 2; pa++) {
                uint32_t Af[4][4];
                const uint32_t slab = stg + pa * SLAB_BYTES;
#pragma unroll
                for (int mt = 0; mt < 4; mt++) {
                    const int row = wm * 64 + mt * 16 + aRow;
                    const uint32_t ad = slab + SWZ(row * 128 + kk * 32 + aCh * 16);
                    LDSM4(Af[mt], ad);
                }
                const int nProd = 2 - pa;
#pragma unroll
                for (int pb = 0; pb < 2; pb++) {
                    if (pb >= nProd) break;
#pragma unroll
                    for (int mt = 0; mt < 4; mt++) {
#pragma unroll
                        for (int nt2 = 0; nt2 < 2; nt2++) {
                            MMA16816(acc[mt][nt2 * 2 + 0], Af[mt], &Bf[pb][nt2 * 4 + 0]);
                            MMA16816(acc[mt][nt2 * 2 + 1], Af[mt], &Bf[pb][nt2 * 4 + 2]);
                        }
                    }
                }
            }
        }
    }

    const int rBase = m0 + wm * 64 + (lane >> 2);
    const int cBase = n0 + wn * 32 + 2 * (lane & 3);
#pragma unroll
    for (int mt = 0; mt < 4; mt++) {
#pragma unroll
        for (int nt = 0; nt < 4; nt++) {
            const int col = cBase + nt * 8;
            const float b0 = bias[col], b1 = bias[col + 1];
            const int r0 = rBase + mt * 16;
            float2 o0 = make_float2(acc[mt][nt][0] + b0, acc[mt][nt][1] + b1);
            float2 o1 = make_float2(acc[mt][nt][2] + b0, acc[mt][nt][3] + b1);
            __stwt((float2*)&g_hall[(size_t)r0 * H_ + col], o0);
            __stwt((float2*)&g_hall[(size_t)(r0 + 8) * H_ + col], o1);
        }
    }
}

// ---------------- fast LIF scan + at-risk flagging (bucketed, flat ids) ----------------
__global__ void __launch_bounds__(256) scan_flag_kernel()
{
    const int idx = blockIdx.x * blockDim.x + threadIdx.x;
    const int flat = idx * 4;
    const float* p = g_hall + (size_t)flat;

    float v[4] = {0.f, 0.f, 0.f, 0.f};
    float z[4] = {0.f, 0.f, 0.f, 0.f};
    float mm[4] = {1e9f, 1e9f, 1e9f, 1e9f};

#pragma unroll 4
    for (int t = 0; t < T_; t++) {
        const float4 hv = __ldcs((const float4*)(p + (size_t)t * ((size_t)B_ * H_)));
        const float hh[4] = {hv.x, hv.y, hv.z, hv.w};
#pragma unroll
        for (int j = 0; j < 4; j++) {
            v[j] = 0.9f * v[j] + hh[j];
            const float d = v[j] - 1.0f;
            mm[j] = fminf(mm[j], fabsf(d));
            z[j] = (d > 0.0f) ? 1.0f : 0.0f;
            v[j] -= z[j];
        }
    }
    *(float4*)&g_z[flat] = make_float4(z[0], z[1], z[2], z[3]);

    const int b = flat / H_;
#pragma unroll
    for (int j = 0; j < 4; j++) {
        if (mm[j] < DELTA) {
            const unsigned int p2 = atomicAdd(&g_bcnt[b], 1u);
            if (p2 < CAPB) g_blist[b * CAPB + p2] = flat + j;
        }
    }
}

// ---------------- fixup: exact h + scan, natural layouts, NHG=32 ----------------
// One CTA per batch row, 128 threads as 16(tg) x 8(jg): thread tile 8t x 4j.
// xs[t][k] (pad 68) and ws[j][k] (pad 68) match global layout: staging is pure
// float4 LDG -> float4 STS, no transpose. Compute: k chunks of 4; per chunk
// 12 LDS.128 + 128 FMA. k-order per (t,j): ktile asc, chunk asc, k asc ==
// validated sequential order; bias at end.
#define FIX_KT 64

__global__ void __launch_bounds__(128) fixup_kernel(const float* __restrict__ x,
                                                    const float* __restrict__ W,
                                                    const float* __restrict__ bias)
{
    __shared__ float xs[T_][FIX_KT + 4];    // 128 x 68 = 34816 B
    __shared__ float ws[NHG][FIX_KT + 4];   // 32 x 68  = 8704 B
    __shared__ float hb[NHG][129];          // 16512 B (scalar stores; scan conflict-free)
    __shared__ int hsm[NHG];
    __shared__ int fsm[NHG];

    const int b = blockIdx.x;
    const unsigned int cnt = min(g_bcnt[b], (unsigned int)CAPB);
    if (cnt == 0) return;
    const int tid = threadIdx.x;
    const int jg = tid & 7;
    const int tg = tid >> 3;
    const int t0 = tg * 8;              // 0..120
    const int j0 = jg * 4;              // 0..28

    for (unsigned int g = 0; g < cnt; g += NHG) {
        const int nh = (int)min((unsigned int)NHG, cnt - g);
        if (tid < NHG) {
            const int fl = (tid < nh) ? g_blist[b * CAPB + g + tid] : -1;
            fsm[tid] = fl;
            hsm[tid] = (fl >= 0) ? (fl % H_) : 0;
        }
        __syncthreads();

        float acc[8][4];
#pragma unroll
        for (int i = 0; i < 8; i++)
#pragma unroll
            for (int j = 0; j < 4; j++) acc[i][j] = 0.0f;

        for (int kt = 0; kt < D_ / FIX_KT; kt++) {      // 8 k-tiles, ascending
            const int k0 = kt * FIX_KT;
            // stage xs[t][0..63]: 2048 float4, 16 per thread, coalesced
#pragma unroll
            for (int i = 0; i < 16; i++) {
                const int idx = i * 128 + tid;
                const int t = idx >> 4;
                const int c4 = idx & 15;
                const float4 v = *(const float4*)(x + ((size_t)t * B_ + b) * D_ + k0 + c4 * 4);
                *(float4*)&xs[t][c4 * 4] = v;
            }
            // stage ws[j][0..63]: 512 float4, 4 per thread
#pragma unroll
            for (int i = 0; i < 4; i++) {
                const int idx = i * 128 + tid;
                const int j = idx >> 4;
                const int c4 = idx & 15;
                float4 wv = make_float4(0.f, 0.f, 0.f, 0.f);
                if (j < nh)
                    wv = *(const float4*)(W + (size_t)hsm[j] * D_ + k0 + c4 * 4);
                *(float4*)&ws[j][c4 * 4] = wv;
            }
            __syncthreads();

#pragma unroll
            for (int kc = 0; kc < FIX_KT / 4; kc++) {   // 16 chunks of 4 k
                float4 wv[4];
#pragma unroll
                for (int jj = 0; jj < 4; jj++)
                    wv[jj] = *(const float4*)&ws[j0 + jj][kc * 4];
#pragma unroll
                for (int i = 0; i < 8; i++) {
                    const float4 xv = *(const float4*)&xs[t0 + i][kc * 4];
#pragma unroll
                    for (int jj = 0; jj < 4; jj++) {
                        acc[i][jj] = fmaf(xv.x, wv[jj].x, acc[i][jj]);
                        acc[i][jj] = fmaf(xv.y, wv[jj].y, acc[i][jj]);
                        acc[i][jj] = fmaf(xv.z, wv[jj].z, acc[i][jj]);
                        acc[i][jj] = fmaf(xv.w, wv[jj].w, acc[i][jj]);
                    }
                }
            }
            __syncthreads();
        }

        // h = acc + bias -> hb[j][t] (scalar stores)
#pragma unroll
        for (int jj = 0; jj < 4; jj++) {
            const float bv = bias[hsm[j0 + jj]];
#pragma unroll
            for (int i = 0; i < 8; i++)
                hb[j0 + jj][t0 + i] = acc[i][jj] + bv;
        }
        __syncthreads();

        // scan the group's neurons (threads 0..nh-1); hb stride 129 -> conflict-free
        if (tid < nh) {
            const float* hp = hb[tid];
            float v = 0.0f, z = 0.0f;
#pragma unroll 4
            for (int t = 0; t < T_; t++) {
                v = 0.9f * v + hp[t];
                z = (v > 1.0f) ? 1.0f : 0.0f;
                v -= z;
            }
            g_z[fsm[tid]] = z;
        }
        __syncthreads();
    }
}

// ---------------- classifier ----------------
__global__ void __launch_bounds__(256) cls_kernel(const float* __restrict__ Wout,
                                                  const float* __restrict__ bout,
                                                  float* __restrict__ out)
{
    const int gw = (blockIdx.x * blockDim.x + threadIdx.x) >> 5;
    const int lane = threadIdx.x & 31;
    if (gw >= B_ * C_) return;
    const int b = gw / C_;
    const int c = gw % C_;

    const float* zp = g_z + (size_t)b * H_;
    const float* wp = Wout + (size_t)c * H_;

    float s = 0.0f;
#pragma unroll
    for (int h = lane * 4; h < H_; h += 32 * 4) {
        const float4 zz = *(const float4*)&zp[h];
        const float4 ww = *(const float4*)&wp[h];
        s = fmaf(zz.x, ww.x, s);
        s = fmaf(zz.y, ww.y, s);
        s = fmaf(zz.z, ww.z, s);
        s = fmaf(zz.w, ww.w, s);
    }
#pragma unroll
    for (int o = 16; o > 0; o >>= 1)
        s += __shfl_xor_sync(0xffffffffu, s, o);
    if (lane == 0) out[(size_t)b * C_ + c] = s + bout[c];
}

// ---------------------------------------------------------------------------
extern "C" void kernel_launch(void* const* d_in, const int* in_sizes, int n_in,
                              void* d_out, int out_size)
{
    const float* x     = (const float*)d_in[0];  // [T, B, D]
    const float* W_in  = (const float*)d_in[1];  // [H, D]
    const float* b_in  = (const float*)d_in[2];  // [H]
    const float* W_out = (const float*)d_in[3];  // [C, H]
    const float* b_out = (const float*)d_in[4];  // [C]
    float* out = (float*)d_out;                  // [B, C]

    cudaFuncSetAttribute(gemm_hmma_kernel, cudaFuncAttributeMaxDynamicSharedMemorySize, SMEM_TOTAL);

    zero_cnt_kernel<<<1, 512>>>();
    splitA_kernel<<<(M_ * D_ / 4 + 255) / 256, 256>>>(x);
    splitB_kernel<<<(H_ * D_ / 4 + 255) / 256, 256>>>(W_in);

    dim3 g(H_ / 128, M_ / 128);                  // 16 x 512 CTAs
    gemm_hmma_kernel<<<g, 256, SMEM_TOTAL>>>(b_in);

    scan_flag_kernel<<<(B_ * H_ / 4) / 256, 256>>>();

    fixup_kernel<<<B_, 128>>>(x, W_in, b_in);

    cls_kernel<<<(B_ * C_ * 32) / 256, 256>>>(W_out, b_out, out);
}

// round 15
// speedup vs baseline: 2.3908x; 1.0083x over previous
#include <cuda_runtime.h>
#include <cuda_bf16.h>
#include <cstdint>

#define T_ 128
#define B_ 512
#define D_ 512
#define H_ 2048
#define C_ 18
#define M_ (T_ * B_)   // 65536

#define CAPB 2048            // per-batch-row capacity (expect ~40)
#define DELTA 2.5e-4f        // flag margin
#define NHG 32               // h-group size in fixup

// ---------------- device scratch (allocation-free rule) ----------------
__device__ __nv_bfloat16 g_Ahi[(size_t)M_ * D_];
__device__ __nv_bfloat16 g_Amid[(size_t)M_ * D_];
__device__ __nv_bfloat16 g_Bhi[(size_t)H_ * D_];
__device__ __nv_bfloat16 g_Bmid[(size_t)H_ * D_];
__device__ float g_hall[(size_t)M_ * H_];      // 512 MB (fast h)
__device__ float g_z[B_ * H_];
__device__ unsigned int g_bcnt[B_];
__device__ int g_blist[B_ * CAPB];             // flat neuron ids per bucket

// ---------------- helpers ----------------
static __device__ __forceinline__ uint32_t s2u(const void* p) {
    uint32_t a;
    asm("{ .reg .u64 t; cvta.to.shared.u64 t, %1; cvt.u32.u64 %0, t; }" : "=r"(a) : "l"(p));
    return a;
}
// SW64 swizzle for 64-byte rows: bits[5:4] ^= bits[8:7]
#define SWZ64(o) ((o) ^ (((o) >> 3) & 0x30))

#define LDSM4(r, a) \
    asm volatile("ldmatrix.sync.aligned.m8n8.x4.shared.b16 {%0,%1,%2,%3}, [%4];" \
                 : "=r"((r)[0]), "=r"((r)[1]), "=r"((r)[2]), "=r"((r)[3]) : "r"(a))

#define MMA16816(d, a, b) \
    asm volatile("mma.sync.aligned.m16n8k16.row.col.f32.bf16.bf16.f32 " \
                 "{%0,%1,%2,%3}, {%4,%5,%6,%7}, {%8,%9}, {%0,%1,%2,%3};" \
                 : "+f"((d)[0]), "+f"((d)[1]), "+f"((d)[2]), "+f"((d)[3]) \
                 : "r"((a)[0]), "r"((a)[1]), "r"((a)[2]), "r"((a)[3]), \
                   "r"((b)[0]), "r"((b)[1]))

// ---------------- split: fp32 -> exact 2-way bf16 (hi + mid) ----------------
static __device__ __forceinline__ uint32_t pk(__nv_bfloat16 a, __nv_bfloat16 b) {
    return (uint32_t)__bfloat16_as_ushort(a) | ((uint32_t)__bfloat16_as_ushort(b) << 16);
}

static __device__ __forceinline__ void split2(const float* __restrict__ src,
                                              __nv_bfloat16* __restrict__ hi,
                                              __nv_bfloat16* __restrict__ mid,
                                              int i)
{
    float4 v = ((const float4*)src)[i];
    float a[4] = {v.x, v.y, v.z, v.w};
    __nv_bfloat16 h[4], m[4];
#pragma unroll
    for (int j = 0; j < 4; j++) {
        float x = a[j];
        __nv_bfloat16 xh = __float2bfloat16(x);
        float r1 = x - __bfloat162float(xh);
        h[j] = xh; m[j] = __float2bfloat16(r1);
    }
    uint2 oh, om;
    oh.x = pk(h[0], h[1]); oh.y = pk(h[2], h[3]);
    om.x = pk(m[0], m[1]); om.y = pk(m[2], m[3]);
    *(uint2*)(hi  + 4 * (size_t)i) = oh;
    *(uint2*)(mid + 4 * (size_t)i) = om;
}

__global__ void __launch_bounds__(256) splitA_kernel(const float* __restrict__ src) {
    int i = blockIdx.x * blockDim.x + threadIdx.x;
    if (i < M_ * D_ / 4) split2(src, g_Ahi, g_Amid, i);
}
__global__ void __launch_bounds__(256) splitB_kernel(const float* __restrict__ src) {
    int i = blockIdx.x * blockDim.x + threadIdx.x;
    if (i < H_ * D_ / 4) split2(src, g_Bhi, g_Bmid, i);
}

__global__ void __launch_bounds__(512) zero_cnt_kernel() {
    g_bcnt[threadIdx.x] = 0u;
}

// ---------------- fast HMMA GEMM: 3 products (hh, hm, mh) ----------------
// Round-15 change: KC=32 (64B rows, SW64), stage 32 KB, 3-ring = 96 KB/CTA,
// 2 CTAs/SM (16 warps) so barrier stalls in one CTA are covered by the other.
// Global k-order per product unchanged (stages asc x kk asc) -> h bit-identical.
#define TILE_K 32
#define SLAB_BYTES 8192                   // 128 rows x 64 B
#define STAGE_BYTES (4 * SLAB_BYTES)      // 32 KB
#define SMEM_TOTAL (3 * STAGE_BYTES)      // 96 KB

__global__ void __launch_bounds__(256, 2) gemm_hmma_kernel(const float* __restrict__ bias)
{
    extern __shared__ char smem[];
    const uint32_t sb = s2u(smem);
    const int tid = threadIdx.x;
    const int wid = tid >> 5;
    const int lane = tid & 31;
    const int wm = wid >> 2;
    const int wn = wid & 3;

    const int m0 = (int)blockIdx.y * 128;
    const int n0 = (int)blockIdx.x * 128;

    const __nv_bfloat16* planes[4] = {
        g_Ahi  + (size_t)m0 * D_, g_Amid + (size_t)m0 * D_,
        g_Bhi  + (size_t)n0 * D_, g_Bmid + (size_t)n0 * D_ };

    auto load_stage = [&](int buf, int kBase) {
        const uint32_t base = sb + buf * STAGE_BYTES;
#pragma unroll
        for (int j = 0; j < 4; j++) {
            const __nv_bfloat16* p = planes[j];
            const uint32_t slab = base + j * SLAB_BYTES;
#pragma unroll
            for (int i = 0; i < 2; i++) {
                const int chunk = i * 256 + tid;   // 0..511 (16B chunks)
                const int row = chunk >> 2;        // 0..127
                const int cc = chunk & 3;          // 0..3
                const uint32_t dst = slab + SWZ64(row * 64 + cc * 16);
                const void* src = p + (size_t)row * D_ + kBase + cc * 8;
                asm volatile("cp.async.cg.shared.global [%0], [%1], 16;" :: "r"(dst), "l"(src));
            }
        }
        asm volatile("cp.async.commit_group;" ::: "memory");
    };

    float acc[4][4][4];
#pragma unroll
    for (int a = 0; a < 4; a++)
#pragma unroll
        for (int b = 0; b < 4; b++)
#pragma unroll
            for (int r = 0; r < 4; r++) acc[a][b][r] = 0.0f;

    load_stage(0, 0);
    load_stage(1, TILE_K);

    const int aRow = (lane & 15);
    const int aCh  = (lane >> 4);
    const int bRow = (lane & 7) + ((lane >> 4) << 3);
    const int bCh  = (lane >> 3) & 1;

    const int NSTAGE = D_ / TILE_K;   // 16
    for (int s = 0; s < NSTAGE; s++) {
        if (s < NSTAGE - 1)
            asm volatile("cp.async.wait_group 1;" ::: "memory");
        else
            asm volatile("cp.async.wait_group 0;" ::: "memory");
        __syncthreads();
        if (s + 2 < NSTAGE) load_stage((s + 2) % 3, (s + 2) * TILE_K);

        const uint32_t stg = sb + (uint32_t)(s % 3) * STAGE_BYTES;
#pragma unroll
        for (int kk = 0; kk < 2; kk++) {
            uint32_t Bf[2][8];
#pragma unroll
            for (int pb = 0; pb < 2; pb++) {
                const uint32_t slab = stg + (2 + pb) * SLAB_BYTES;
#pragma unroll
                for (int nt2 = 0; nt2 < 2; nt2++) {
                    const int row = wn * 32 + nt2 * 16 + bRow;
                    const uint32_t ad = slab + SWZ64(row * 64 + kk * 32 + bCh * 16);
                    LDSM4(&Bf[pb][nt2 * 4], ad);
                }
            }
#pragma unroll
            for (int pa = 0; pa < 2; pa++) {
                uint32_t Af[4][4];
                const uint32_t slab = stg + pa * SLAB_BYTES;
#pragma unroll
                for (int mt = 0; mt < 4; mt++) {
                    const int row = wm * 64 + mt * 16 + aRow;
                    const uint32_t ad = slab + SWZ64(row * 64 + kk * 32 + aCh * 16);
                    LDSM4(Af[mt], ad);
                }
                const int nProd = 2 - pa;
#pragma unroll
                for (int pb = 0; pb < 2; pb++) {
                    if (pb >= nProd) break;
#pragma unroll
                    for (int mt = 0; mt < 4; mt++) {
#pragma unroll
                        for (int nt2 = 0; nt2 < 2; nt2++) {
                            MMA16816(acc[mt][nt2 * 2 + 0], Af[mt], &Bf[pb][nt2 * 4 + 0]);
                            MMA16816(acc[mt][nt2 * 2 + 1], Af[mt], &Bf[pb][nt2 * 4 + 2]);
                        }
                    }
                }
            }
        }
    }

    const int rBase = m0 + wm * 64 + (lane >> 2);
    const int cBase = n0 + wn * 32 + 2 * (lane & 3);
#pragma unroll
    for (int mt = 0; mt < 4; mt++) {
#pragma unroll
        for (int nt = 0; nt < 4; nt++) {
            const int col = cBase + nt * 8;
            const float b0 = bias[col], b1 = bias[col + 1];
            const int r0 = rBase + mt * 16;
            float2 o0 = make_float2(acc[mt][nt][0] + b0, acc[mt][nt][1] + b1);
            float2 o1 = make_float2(acc[mt][nt][2] + b0, acc[mt][nt][3] + b1);
            __stwt((float2*)&g_hall[(size_t)r0 * H_ + col], o0);
            __stwt((float2*)&g_hall[(size_t)(r0 + 8) * H_ + col], o1);
        }
    }
}

// ---------------- fast LIF scan + at-risk flagging (bucketed, flat ids) ----------------
__global__ void __launch_bounds__(256) scan_flag_kernel()
{
    const int idx = blockIdx.x * blockDim.x + threadIdx.x;
    const int flat = idx * 4;
    const float* p = g_hall + (size_t)flat;

    float v[4] = {0.f, 0.f, 0.f, 0.f};
    float z[4] = {0.f, 0.f, 0.f, 0.f};
    float mm[4] = {1e9f, 1e9f, 1e9f, 1e9f};

#pragma unroll 4
    for (int t = 0; t < T_; t++) {
        const float4 hv = __ldcs((const float4*)(p + (size_t)t * ((size_t)B_ * H_)));
        const float hh[4] = {hv.x, hv.y, hv.z, hv.w};
#pragma unroll
        for (int j = 0; j < 4; j++) {
            v[j] = 0.9f * v[j] + hh[j];
            const float d = v[j] - 1.0f;
            mm[j] = fminf(mm[j], fabsf(d));
            z[j] = (d > 0.0f) ? 1.0f : 0.0f;
            v[j] -= z[j];
        }
    }
    *(float4*)&g_z[flat] = make_float4(z[0], z[1], z[2], z[3]);

    const int b = flat / H_;
#pragma unroll
    for (int j = 0; j < 4; j++) {
        if (mm[j] < DELTA) {
            const unsigned int p2 = atomicAdd(&g_bcnt[b], 1u);
            if (p2 < CAPB) g_blist[b * CAPB + p2] = flat + j;
        }
    }
}

// ---------------- fixup: exact h + scan, natural layouts, NHG=32 ----------------
#define FIX_KT 64

__global__ void __launch_bounds__(128) fixup_kernel(const float* __restrict__ x,
                                                    const float* __restrict__ W,
                                                    const float* __restrict__ bias)
{
    __shared__ float xs[T_][FIX_KT + 4];    // 128 x 68 = 34816 B
    __shared__ float ws[NHG][FIX_KT + 4];   // 32 x 68  = 8704 B
    __shared__ float hb[NHG][129];          // 16512 B
    __shared__ int hsm[NHG];
    __shared__ int fsm[NHG];

    const int b = blockIdx.x;
    const unsigned int cnt = min(g_bcnt[b], (unsigned int)CAPB);
    if (cnt == 0) return;
    const int tid = threadIdx.x;
    const int jg = tid & 7;
    const int tg = tid >> 3;
    const int t0 = tg * 8;
    const int j0 = jg * 4;

    for (unsigned int g = 0; g < cnt; g += NHG) {
        const int nh = (int)min((unsigned int)NHG, cnt - g);
        if (tid < NHG) {
            const int fl = (tid < nh) ? g_blist[b * CAPB + g + tid] : -1;
            fsm[tid] = fl;
            hsm[tid] = (fl >= 0) ? (fl % H_) : 0;
        }
        __syncthreads();

        float acc[8][4];
#pragma unroll
        for (int i = 0; i < 8; i++)
#pragma unroll
            for (int j = 0; j < 4; j++) acc[i][j] = 0.0f;

        for (int kt = 0; kt < D_ / FIX_KT; kt++) {
            const int k0 = kt * FIX_KT;
#pragma unroll
            for (int i = 0; i < 16; i++) {
                const int idx = i * 128 + tid;
                const int t = idx >> 4;
                const int c4 = idx & 15;
                const float4 v = *(const float4*)(x + ((size_t)t * B_ + b) * D_ + k0 + c4 * 4);
                *(float4*)&xs[t][c4 * 4] = v;
            }
#pragma unroll
            for (int i = 0; i < 4; i++) {
                const int idx = i * 128 + tid;
                const int j = idx >> 4;
                const int c4 = idx & 15;
                float4 wv = make_float4(0.f, 0.f, 0.f, 0.f);
                if (j < nh)
                    wv = *(const float4*)(W + (size_t)hsm[j] * D_ + k0 + c4 * 4);
                *(float4*)&ws[j][c4 * 4] = wv;
            }
            __syncthreads();

#pragma unroll
            for (int kc = 0; kc < FIX_KT / 4; kc++) {
                float4 wv[4];
#pragma unroll
                for (int jj = 0; jj < 4; jj++)
                    wv[jj] = *(const float4*)&ws[j0 + jj][kc * 4];
#pragma unroll
                for (int i = 0; i < 8; i++) {
                    const float4 xv = *(const float4*)&xs[t0 + i][kc * 4];
#pragma unroll
                    for (int jj = 0; jj < 4; jj++) {
                        acc[i][jj] = fmaf(xv.x, wv[jj].x, acc[i][jj]);
                        acc[i][jj] = fmaf(xv.y, wv[jj].y, acc[i][jj]);
                        acc[i][jj] = fmaf(xv.z, wv[jj].z, acc[i][jj]);
                        acc[i][jj] = fmaf(xv.w, wv[jj].w, acc[i][jj]);
                    }
                }
            }
            __syncthreads();
        }

#pragma unroll
        for (int jj = 0; jj < 4; jj++) {
            const float bv = bias[hsm[j0 + jj]];
#pragma unroll
            for (int i = 0; i < 8; i++)
                hb[j0 + jj][t0 + i] = acc[i][jj] + bv;
        }
        __syncthreads();

        if (tid < nh) {
            const float* hp = hb[tid];
            float v = 0.0f, z = 0.0f;
#pragma unroll 4
            for (int t = 0; t < T_; t++) {
                v = 0.9f * v + hp[t];
                z = (v > 1.0f) ? 1.0f : 0.0f;
                v -= z;
            }
            g_z[fsm[tid]] = z;
        }
        __syncthreads();
    }
}

// ---------------- classifier ----------------
__global__ void __launch_bounds__(256) cls_kernel(const float* __restrict__ Wout,
                                                  const float* __restrict__ bout,
                                                  float* __restrict__ out)
{
    const int gw = (blockIdx.x * blockDim.x + threadIdx.x) >> 5;
    const int lane = threadIdx.x & 31;
    if (gw >= B_ * C_) return;
    const int b = gw / C_;
    const int c = gw % C_;

    const float* zp = g_z + (size_t)b * H_;
    const float* wp = Wout + (size_t)c * H_;

    float s = 0.0f;
#pragma unroll
    for (int h = lane * 4; h < H_; h += 32 * 4) {
        const float4 zz = *(const float4*)&zp[h];
        const float4 ww = *(const float4*)&wp[h];
        s = fmaf(zz.x, ww.x, s);
        s = fmaf(zz.y, ww.y, s);
        s = fmaf(zz.z, ww.z, s);
        s = fmaf(zz.w, ww.w, s);
    }
#pragma unroll
    for (int o = 16; o > 0; o >>= 1)
        s += __shfl_xor_sync(0xffffffffu, s, o);
    if (lane == 0) out[(size_t)b * C_ + c] = s + bout[c];
}

// ---------------------------------------------------------------------------
extern "C" void kernel_launch(void* const* d_in, const int* in_sizes, int n_in,
                              void* d_out, int out_size)
{
    const float* x     = (const float*)d_in[0];  // [T, B, D]
    const float* W_in  = (const float*)d_in[1];  // [H, D]
    const float* b_in  = (const float*)d_in[2];  // [H]
    const float* W_out = (const float*)d_in[3];  // [C, H]
    const float* b_out = (const float*)d_in[4];  // [C]
    float* out = (float*)d_out;                  // [B, C]

    cudaFuncSetAttribute(gemm_hmma_kernel, cudaFuncAttributeMaxDynamicSharedMemorySize, SMEM_TOTAL);

    zero_cnt_kernel<<<1, 512>>>();
    splitA_kernel<<<(M_ * D_ / 4 + 255) / 256, 256>>>(x);
    splitB_kernel<<<(H_ * D_ / 4 + 255) / 256, 256>>>(W_in);

    dim3 g(H_ / 128, M_ / 128);                  // 16 x 512 CTAs
    gemm_hmma_kernel<<<g, 256, SMEM_TOTAL>>>(b_in);

    scan_flag_kernel<<<(B_ * H_ / 4) / 256, 256>>>();

    fixup_kernel<<<B_, 128>>>(x, W_in, b_in);

    cls_kernel<<<(B_ * C_ * 32) / 256, 256>>>(W_out, b_out, out);
}

// round 16
// speedup vs baseline: 2.5134x; 1.0513x over previous
#include <cuda_runtime.h>
#include <cuda_bf16.h>
#include <cstdint>

#define T_ 128
#define B_ 512
#define D_ 512
#define H_ 2048
#define C_ 18
#define M_ (T_ * B_)   // 65536

#define CAPB 2048            // per-batch-row capacity (expect ~40)
#define DELTA 2.5e-4f        // flag margin
#define NHG 32               // h-group size in fixup

// ---------------- device scratch (allocation-free rule) ----------------
__device__ __nv_bfloat16 g_Ahi[(size_t)M_ * D_];
__device__ __nv_bfloat16 g_Amid[(size_t)M_ * D_];
__device__ __nv_bfloat16 g_Bhi[(size_t)H_ * D_];
__device__ __nv_bfloat16 g_Bmid[(size_t)H_ * D_];
__device__ float g_hall[(size_t)M_ * H_];      // 512 MB (fast h)
__device__ float g_z[B_ * H_];
__device__ unsigned int g_bcnt[B_];
__device__ int g_blist[B_ * CAPB];             // flat neuron ids per bucket

// ---------------- helpers ----------------
static __device__ __forceinline__ uint32_t s2u(const void* p) {
    uint32_t a;
    asm("{ .reg .u64 t; cvta.to.shared.u64 t, %1; cvt.u32.u64 %0, t; }" : "=r"(a) : "l"(p));
    return a;
}
// SW64 swizzle for 64-byte rows: bits[5:4] ^= bits[8:7]
#define SWZ64(o) ((o) ^ (((o) >> 3) & 0x30))

#define LDSM4(r, a) \
    asm volatile("ldmatrix.sync.aligned.m8n8.x4.shared.b16 {%0,%1,%2,%3}, [%4];" \
                 : "=r"((r)[0]), "=r"((r)[1]), "=r"((r)[2]), "=r"((r)[3]) : "r"(a))

#define MMA16816(d, a, b) \
    asm volatile("mma.sync.aligned.m16n8k16.row.col.f32.bf16.bf16.f32 " \
                 "{%0,%1,%2,%3}, {%4,%5,%6,%7}, {%8,%9}, {%0,%1,%2,%3};" \
                 : "+f"((d)[0]), "+f"((d)[1]), "+f"((d)[2]), "+f"((d)[3]) \
                 : "r"((a)[0]), "r"((a)[1]), "r"((a)[2]), "r"((a)[3]), \
                   "r"((b)[0]), "r"((b)[1]))

// mbarrier primitives (base PTX, sm_80+; compiled fine on this toolchain in R2)
#define MBAR_INIT(a, c) \
    asm volatile("mbarrier.init.shared.b64 [%0], %1;" :: "r"(a), "r"(c) : "memory")
#define MBAR_ARRIVE(a) \
    asm volatile("mbarrier.arrive.shared.b64 _, [%0];" :: "r"(a) : "memory")
#define CPASYNC_ARRIVE(a) \
    asm volatile("cp.async.mbarrier.arrive.noinc.shared.b64 [%0];" :: "r"(a) : "memory")
#define MBAR_WAIT(addr, par) \
    asm volatile("{\n\t.reg .pred P;\n" \
                 "W_%=:\n\t" \
                 "mbarrier.try_wait.parity.acquire.cta.shared::cta.b64 P, [%0], %1, 0x989680;\n\t" \
                 "@P bra D_%=;\n\t" \
                 "bra W_%=;\n" \
                 "D_%=:\n\t}" :: "r"(addr), "r"(par) : "memory")

// ---------------- split: fp32 -> exact 2-way bf16 (hi + mid) ----------------
static __device__ __forceinline__ uint32_t pk(__nv_bfloat16 a, __nv_bfloat16 b) {
    return (uint32_t)__bfloat16_as_ushort(a) | ((uint32_t)__bfloat16_as_ushort(b) << 16);
}

static __device__ __forceinline__ void split2(const float* __restrict__ src,
                                              __nv_bfloat16* __restrict__ hi,
                                              __nv_bfloat16* __restrict__ mid,
                                              int i)
{
    float4 v = ((const float4*)src)[i];
    float a[4] = {v.x, v.y, v.z, v.w};
    __nv_bfloat16 h[4], m[4];
#pragma unroll
    for (int j = 0; j < 4; j++) {
        float x = a[j];
        __nv_bfloat16 xh = __float2bfloat16(x);
        float r1 = x - __bfloat162float(xh);
        h[j] = xh; m[j] = __float2bfloat16(r1);
    }
    uint2 oh, om;
    oh.x = pk(h[0], h[1]); oh.y = pk(h[2], h[3]);
    om.x = pk(m[0], m[1]); om.y = pk(m[2], m[3]);
    *(uint2*)(hi  + 4 * (size_t)i) = oh;
    *(uint2*)(mid + 4 * (size_t)i) = om;
}

__global__ void __launch_bounds__(256) splitA_kernel(const float* __restrict__ src) {
    int i = blockIdx.x * blockDim.x + threadIdx.x;
    if (i < M_ * D_ / 4) split2(src, g_Ahi, g_Amid, i);
}
__global__ void __launch_bounds__(256) splitB_kernel(const float* __restrict__ src) {
    int i = blockIdx.x * blockDim.x + threadIdx.x;
    if (i < H_ * D_ / 4) split2(src, g_Bhi, g_Bmid, i);
}

__global__ void __launch_bounds__(512) zero_cnt_kernel() {
    g_bcnt[threadIdx.x] = 0u;
}

// ---------------- fast HMMA GEMM: 3 products (hh, hm, mh) ----------------
// Round-16: mbarrier producer/consumer pipeline replaces per-stage
// __syncthreads. full[b]: 256 x cp.async.mbarrier.arrive.noinc;
// empty[b]: 8 warp arrivals (lane0, after the stage's last LDSM).
// Warps free-run; fill backpressure is per-buffer. Per-thread MMA order
// unchanged -> h bit-identical to rounds 11-15.
#define TILE_K 32
#define SLAB_BYTES 8192                   // 128 rows x 64 B
#define STAGE_BYTES (4 * SLAB_BYTES)      // 32 KB
#define SMEM_HDR 1024                     // mbarriers live here
#define SMEM_TOTAL (SMEM_HDR + 3 * STAGE_BYTES)   // 99328 B -> 2 CTAs/SM

__global__ void __launch_bounds__(256, 2) gemm_hmma_kernel(const float* __restrict__ bias)
{
    extern __shared__ char smem[];
    const uint32_t sb = s2u(smem);
    const int tid = threadIdx.x;
    const int wid = tid >> 5;
    const int lane = tid & 31;
    const int wm = wid >> 2;
    const int wn = wid & 3;

    const int m0 = (int)blockIdx.y * 128;
    const int n0 = (int)blockIdx.x * 128;

    // mbarrier addresses: full[0..2] at sb+0,8,16; empty[0..2] at sb+24,32,40
    if (tid == 0) {
#pragma unroll
        for (int i = 0; i < 3; i++) {
            MBAR_INIT(sb + 8u * i, 256u);        // full[i]
            MBAR_INIT(sb + 24u + 8u * i, 8u);    // empty[i]
        }
    }
    __syncthreads();

    const __nv_bfloat16* planes[4] = {
        g_Ahi  + (size_t)m0 * D_, g_Amid + (size_t)m0 * D_,
        g_Bhi  + (size_t)n0 * D_, g_Bmid + (size_t)n0 * D_ };

    auto load_stage = [&](int buf, int kBase) {
        const uint32_t base = sb + SMEM_HDR + buf * STAGE_BYTES;
#pragma unroll
        for (int j = 0; j < 4; j++) {
            const __nv_bfloat16* p = planes[j];
            const uint32_t slab = base + j * SLAB_BYTES;
#pragma unroll
            for (int i = 0; i < 2; i++) {
                const int chunk = i * 256 + tid;   // 0..511 (16B chunks)
                const int row = chunk >> 2;        // 0..127
                const int cc = chunk & 3;          // 0..3
                const uint32_t dst = slab + SWZ64(row * 64 + cc * 16);
                const void* src = p + (size_t)row * D_ + kBase + cc * 8;
                asm volatile("cp.async.cg.shared.global [%0], [%1], 16;" :: "r"(dst), "l"(src));
            }
        }
    };

    float acc[4][4][4];
#pragma unroll
    for (int a = 0; a < 4; a++)
#pragma unroll
        for (int b = 0; b < 4; b++)
#pragma unroll
            for (int r = 0; r < 4; r++) acc[a][b][r] = 0.0f;

    // prologue: fill stage 0 (buf0) and stage 1 (buf1); buffers initially free
    load_stage(0, 0);
    CPASYNC_ARRIVE(sb + 0u);
    load_stage(1, TILE_K);
    CPASYNC_ARRIVE(sb + 8u);

    const int aRow = (lane & 15);
    const int aCh  = (lane >> 4);
    const int bRow = (lane & 7) + ((lane >> 4) << 3);
    const int bCh  = (lane >> 3) & 1;

    const int NSTAGE = D_ / TILE_K;   // 16
    for (int s = 0; s < NSTAGE; s++) {
        // producer: fill stage s+2 (issued before consuming s, overlaps MMAs)
        const int st = s + 2;
        if (st < NSTAGE) {
            const int fb = st % 3;
            if (st >= 3) {
                const uint32_t r = (uint32_t)(st / 3);
                MBAR_WAIT(sb + 24u + 8u * fb, (r - 1u) & 1u);   // wait buffer freed
            }
            load_stage(fb, st * TILE_K);
            CPASYNC_ARRIVE(sb + 8u * fb);
        }

        // consumer: wait stage s full
        const int cb = s % 3;
        MBAR_WAIT(sb + 8u * cb, (uint32_t)(s / 3) & 1u);

        const uint32_t stg = sb + SMEM_HDR + (uint32_t)cb * STAGE_BYTES;
#pragma unroll
        for (int kk = 0; kk < 2; kk++) {
            uint32_t Bf[2][8];
#pragma unroll
            for (int pb = 0; pb < 2; pb++) {
                const uint32_t slab = stg + (2 + pb) * SLAB_BYTES;
#pragma unroll
                for (int nt2 = 0; nt2 < 2; nt2++) {
                    const int row = wn * 32 + nt2 * 16 + bRow;
                    const uint32_t ad = slab + SWZ64(row * 64 + kk * 32 + bCh * 16);
                    LDSM4(&Bf[pb][nt2 * 4], ad);
                }
            }
#pragma unroll
            for (int pa = 0; pa < 2; pa++) {
                uint32_t Af[4][4];
                const uint32_t slab = stg + pa * SLAB_BYTES;
#pragma unroll
                for (int mt = 0; mt < 4; mt++) {
                    const int row = wm * 64 + mt * 16 + aRow;
                    const uint32_t ad = slab + SWZ64(row * 64 + kk * 32 + aCh * 16);
                    LDSM4(Af[mt], ad);
                }
                // after the stage's LAST LDSM (kk=1, pa=1), release the buffer
                if (kk == 1 && pa == 1 && lane == 0)
                    MBAR_ARRIVE(sb + 24u + 8u * cb);
                const int nProd = 2 - pa;
#pragma unroll
                for (int pb = 0; pb < 2; pb++) {
                    if (pb >= nProd) break;
#pragma unroll
                    for (int mt = 0; mt < 4; mt++) {
#pragma unroll
                        for (int nt2 = 0; nt2 < 2; nt2++) {
                            MMA16816(acc[mt][nt2 * 2 + 0], Af[mt], &Bf[pb][nt2 * 4 + 0]);
                            MMA16816(acc[mt][nt2 * 2 + 1], Af[mt], &Bf[pb][nt2 * 4 + 2]);
                        }
                    }
                }
            }
        }
    }

    const int rBase = m0 + wm * 64 + (lane >> 2);
    const int cBase = n0 + wn * 32 + 2 * (lane & 3);
#pragma unroll
    for (int mt = 0; mt < 4; mt++) {
#pragma unroll
        for (int nt = 0; nt < 4; nt++) {
            const int col = cBase + nt * 8;
            const float b0 = bias[col], b1 = bias[col + 1];
            const int r0 = rBase + mt * 16;
            float2 o0 = make_float2(acc[mt][nt][0] + b0, acc[mt][nt][1] + b1);
            float2 o1 = make_float2(acc[mt][nt][2] + b0, acc[mt][nt][3] + b1);
            __stwt((float2*)&g_hall[(size_t)r0 * H_ + col], o0);
            __stwt((float2*)&g_hall[(size_t)(r0 + 8) * H_ + col], o1);
        }
    }
}

// ---------------- fast LIF scan + at-risk flagging (bucketed, flat ids) ----------------
__global__ void __launch_bounds__(256) scan_flag_kernel()
{
    const int idx = blockIdx.x * blockDim.x + threadIdx.x;
    const int flat = idx * 4;
    const float* p = g_hall + (size_t)flat;

    float v[4] = {0.f, 0.f, 0.f, 0.f};
    float z[4] = {0.f, 0.f, 0.f, 0.f};
    float mm[4] = {1e9f, 1e9f, 1e9f, 1e9f};

#pragma unroll 4
    for (int t = 0; t < T_; t++) {
        const float4 hv = __ldcs((const float4*)(p + (size_t)t * ((size_t)B_ * H_)));
        const float hh[4] = {hv.x, hv.y, hv.z, hv.w};
#pragma unroll
        for (int j = 0; j < 4; j++) {
            v[j] = 0.9f * v[j] + hh[j];
            const float d = v[j] - 1.0f;
            mm[j] = fminf(mm[j], fabsf(d));
            z[j] = (d > 0.0f) ? 1.0f : 0.0f;
            v[j] -= z[j];
        }
    }
    *(float4*)&g_z[flat] = make_float4(z[0], z[1], z[2], z[3]);

    const int b = flat / H_;
#pragma unroll
    for (int j = 0; j < 4; j++) {
        if (mm[j] < DELTA) {
            const unsigned int p2 = atomicAdd(&g_bcnt[b], 1u);
            if (p2 < CAPB) g_blist[b * CAPB + p2] = flat + j;
        }
    }
}

// ---------------- fixup: exact h + scan, natural layouts, NHG=32 ----------------
#define FIX_KT 64

__global__ void __launch_bounds__(128) fixup_kernel(const float* __restrict__ x,
                                                    const float* __restrict__ W,
                                                    const float* __restrict__ bias)
{
    __shared__ float xs[T_][FIX_KT + 4];
    __shared__ float ws[NHG][FIX_KT + 4];
    __shared__ float hb[NHG][129];
    __shared__ int hsm[NHG];
    __shared__ int fsm[NHG];

    const int b = blockIdx.x;
    const unsigned int cnt = min(g_bcnt[b], (unsigned int)CAPB);
    if (cnt == 0) return;
    const int tid = threadIdx.x;
    const int jg = tid & 7;
    const int tg = tid >> 3;
    const int t0 = tg * 8;
    const int j0 = jg * 4;

    for (unsigned int g = 0; g < cnt; g += NHG) {
        const int nh = (int)min((unsigned int)NHG, cnt - g);
        if (tid < NHG) {
            const int fl = (tid < nh) ? g_blist[b * CAPB + g + tid] : -1;
            fsm[tid] = fl;
            hsm[tid] = (fl >= 0) ? (fl % H_) : 0;
        }
        __syncthreads();

        float acc[8][4];
#pragma unroll
        for (int i = 0; i < 8; i++)
#pragma unroll
            for (int j = 0; j < 4; j++) acc[i][j] = 0.0f;

        for (int kt = 0; kt < D_ / FIX_KT; kt++) {
            const int k0 = kt * FIX_KT;
#pragma unroll
            for (int i = 0; i < 16; i++) {
                const int idx = i * 128 + tid;
                const int t = idx >> 4;
                const int c4 = idx & 15;
                const float4 v = *(const float4*)(x + ((size_t)t * B_ + b) * D_ + k0 + c4 * 4);
                *(float4*)&xs[t][c4 * 4] = v;
            }
#pragma unroll
            for (int i = 0; i < 4; i++) {
                const int idx = i * 128 + tid;
                const int j = idx >> 4;
                const int c4 = idx & 15;
                float4 wv = make_float4(0.f, 0.f, 0.f, 0.f);
                if (j < nh)
                    wv = *(const float4*)(W + (size_t)hsm[j] * D_ + k0 + c4 * 4);
                *(float4*)&ws[j][c4 * 4] = wv;
            }
            __syncthreads();

#pragma unroll
            for (int kc = 0; kc < FIX_KT / 4; kc++) {
                float4 wv[4];
#pragma unroll
                for (int jj = 0; jj < 4; jj++)
                    wv[jj] = *(const float4*)&ws[j0 + jj][kc * 4];
#pragma unroll
                for (int i = 0; i < 8; i++) {
                    const float4 xv = *(const float4*)&xs[t0 + i][kc * 4];
#pragma unroll
                    for (int jj = 0; jj < 4; jj++) {
                        acc[i][jj] = fmaf(xv.x, wv[jj].x, acc[i][jj]);
                        acc[i][jj] = fmaf(xv.y, wv[jj].y, acc[i][jj]);
                        acc[i][jj] = fmaf(xv.z, wv[jj].z, acc[i][jj]);
                        acc[i][jj] = fmaf(xv.w, wv[jj].w, acc[i][jj]);
                    }
                }
            }
            __syncthreads();
        }

#pragma unroll
        for (int jj = 0; jj < 4; jj++) {
            const float bv = bias[hsm[j0 + jj]];
#pragma unroll
            for (int i = 0; i < 8; i++)
                hb[j0 + jj][t0 + i] = acc[i][jj] + bv;
        }
        __syncthreads();

        if (tid < nh) {
            const float* hp = hb[tid];
            float v = 0.0f, z = 0.0f;
#pragma unroll 4
            for (int t = 0; t < T_; t++) {
                v = 0.9f * v + hp[t];
                z = (v > 1.0f) ? 1.0f : 0.0f;
                v -= z;
            }
            g_z[fsm[tid]] = z;
        }
        __syncthreads();
    }
}

// ---------------- classifier ----------------
__global__ void __launch_bounds__(256) cls_kernel(const float* __restrict__ Wout,
                                                  const float* __restrict__ bout,
                                                  float* __restrict__ out)
{
    const int gw = (blockIdx.x * blockDim.x + threadIdx.x) >> 5;
    const int lane = threadIdx.x & 31;
    if (gw >= B_ * C_) return;
    const int b = gw / C_;
    const int c = gw % C_;

    const float* zp = g_z + (size_t)b * H_;
    const float* wp = Wout + (size_t)c * H_;

    float s = 0.0f;
#pragma unroll
    for (int h = lane * 4; h < H_; h += 32 * 4) {
        const float4 zz = *(const float4*)&zp[h];
        const float4 ww = *(const float4*)&wp[h];
        s = fmaf(zz.x, ww.x, s);
        s = fmaf(zz.y, ww.y, s);
        s = fmaf(zz.z, ww.z, s);
        s = fmaf(zz.w, ww.w, s);
    }
#pragma unroll
    for (int o = 16; o > 0; o >>= 1)
        s += __shfl_xor_sync(0xffffffffu, s, o);
    if (lane == 0) out[(size_t)b * C_ + c] = s + bout[c];
}

// ---------------------------------------------------------------------------
extern "C" void kernel_launch(void* const* d_in, const int* in_sizes, int n_in,
                              void* d_out, int out_size)
{
    const float* x     = (const float*)d_in[0];  // [T, B, D]
    const float* W_in  = (const float*)d_in[1];  // [H, D]
    const float* b_in  = (const float*)d_in[2];  // [H]
    const float* W_out = (const float*)d_in[3];  // [C, H]
    const float* b_out = (const float*)d_in[4];  // [C]
    float* out = (float*)d_out;                  // [B, C]

    cudaFuncSetAttribute(gemm_hmma_kernel, cudaFuncAttributeMaxDynamicSharedMemorySize, SMEM_TOTAL);

    zero_cnt_kernel<<<1, 512>>>();
    splitA_kernel<<<(M_ * D_ / 4 + 255) / 256, 256>>>(x);
    splitB_kernel<<<(H_ * D_ / 4 + 255) / 256, 256>>>(W_in);

    dim3 g(H_ / 128, M_ / 128);                  // 16 x 512 CTAs
    gemm_hmma_kernel<<<g, 256, SMEM_TOTAL>>>(b_in);

    scan_flag_kernel<<<(B_ * H_ / 4) / 256, 256>>>();

    fixup_kernel<<<B_, 128>>>(x, W_in, b_in);

    cls_kernel<<<(B_ * C_ * 32) / 256, 256>>>(W_out, b_out, out);
}

// round 17
// speedup vs baseline: 2.6341x; 1.0480x over previous
#include <cuda_runtime.h>
#include <cuda_bf16.h>
#include <cstdint>

#define T_ 128
#define B_ 512
#define D_ 512
#define H_ 2048
#define C_ 18
#define M_ (T_ * B_)   // 65536

#define CAPB 2048            // per-batch-row capacity (expect ~40)
#define DELTA 2.5e-4f        // flag margin
#define NHG 32               // h-group size in fixup

// ---------------- device scratch (allocation-free rule) ----------------
__device__ __nv_bfloat16 g_Ahi[(size_t)M_ * D_];
__device__ __nv_bfloat16 g_Amid[(size_t)M_ * D_];
__device__ __nv_bfloat16 g_Bhi[(size_t)H_ * D_];
__device__ __nv_bfloat16 g_Bmid[(size_t)H_ * D_];
__device__ float g_z[B_ * H_];
__device__ unsigned int g_bcnt[B_];
__device__ int g_blist[B_ * CAPB];             // flat neuron ids per bucket

// ---------------- helpers ----------------
static __device__ __forceinline__ uint32_t s2u(const void* p) {
    uint32_t a;
    asm("{ .reg .u64 t; cvta.to.shared.u64 t, %1; cvt.u32.u64 %0, t; }" : "=r"(a) : "l"(p));
    return a;
}
// SW64 swizzle for 64-byte rows: bits[5:4] ^= bits[8:7]
#define SWZ64(o) ((o) ^ (((o) >> 3) & 0x30))

#define LDSM4(r, a) \
    asm volatile("ldmatrix.sync.aligned.m8n8.x4.shared.b16 {%0,%1,%2,%3}, [%4];" \
                 : "=r"((r)[0]), "=r"((r)[1]), "=r"((r)[2]), "=r"((r)[3]) : "r"(a))

#define MMA16816(d, a, b) \
    asm volatile("mma.sync.aligned.m16n8k16.row.col.f32.bf16.bf16.f32 " \
                 "{%0,%1,%2,%3}, {%4,%5,%6,%7}, {%8,%9}, {%0,%1,%2,%3};" \
                 : "+f"((d)[0]), "+f"((d)[1]), "+f"((d)[2]), "+f"((d)[3]) \
                 : "r"((a)[0]), "r"((a)[1]), "r"((a)[2]), "r"((a)[3]), \
                   "r"((b)[0]), "r"((b)[1]))

// mbarrier primitives
#define MBAR_INIT(a, c) \
    asm volatile("mbarrier.init.shared.b64 [%0], %1;" :: "r"(a), "r"(c) : "memory")
#define MBAR_ARRIVE(a) \
    asm volatile("mbarrier.arrive.shared.b64 _, [%0];" :: "r"(a) : "memory")
#define CPASYNC_ARRIVE(a) \
    asm volatile("cp.async.mbarrier.arrive.noinc.shared.b64 [%0];" :: "r"(a) : "memory")
#define MBAR_WAIT(addr, par) \
    asm volatile("{\n\t.reg .pred P;\n" \
                 "W_%=:\n\t" \
                 "mbarrier.try_wait.parity.acquire.cta.shared::cta.b64 P, [%0], %1, 0x989680;\n\t" \
                 "@P bra D_%=;\n\t" \
                 "bra W_%=;\n" \
                 "D_%=:\n\t}" :: "r"(addr), "r"(par) : "memory")

// ---------------- split: fp32 -> exact 2-way bf16 (hi + mid) ----------------
static __device__ __forceinline__ uint32_t pk(__nv_bfloat16 a, __nv_bfloat16 b) {
    return (uint32_t)__bfloat16_as_ushort(a) | ((uint32_t)__bfloat16_as_ushort(b) << 16);
}

static __device__ __forceinline__ void split2(const float* __restrict__ src,
                                              __nv_bfloat16* __restrict__ hi,
                                              __nv_bfloat16* __restrict__ mid,
                                              int i)
{
    float4 v = ((const float4*)src)[i];
    float a[4] = {v.x, v.y, v.z, v.w};
    __nv_bfloat16 h[4], m[4];
#pragma unroll
    for (int j = 0; j < 4; j++) {
        float x = a[j];
        __nv_bfloat16 xh = __float2bfloat16(x);
        float r1 = x - __bfloat162float(xh);
        h[j] = xh; m[j] = __float2bfloat16(r1);
    }
    uint2 oh, om;
    oh.x = pk(h[0], h[1]); oh.y = pk(h[2], h[3]);
    om.x = pk(m[0], m[1]); om.y = pk(m[2], m[3]);
    *(uint2*)(hi  + 4 * (size_t)i) = oh;
    *(uint2*)(mid + 4 * (size_t)i) = om;
}

__global__ void __launch_bounds__(256) splitA_kernel(const float* __restrict__ src) {
    int i = blockIdx.x * blockDim.x + threadIdx.x;
    if (i < M_ * D_ / 4) split2(src, g_Ahi, g_Amid, i);
}
__global__ void __launch_bounds__(256) splitB_kernel(const float* __restrict__ src) {
    int i = blockIdx.x * blockDim.x + threadIdx.x;
    if (i < H_ * D_ / 4) split2(src, g_Bhi, g_Bmid, i);
}

__global__ void __launch_bounds__(512) zero_cnt_kernel() {
    g_bcnt[threadIdx.x] = 0u;
}

// ---------------- fused HMMA GEMM + LIF scan + flagging ----------------
// Round-17: m-tile = ALL 128 t's for ONE b (A rows at (t*B+b)*D, stride B*D).
// grid = (16 h-tiles, 512 b). After the mainloop the pipeline buffers are
// repurposed as hb[128h][129t]; acc+bias transposed in, threads 0..127 scan
// one h each (same expressions and t-order as the old scan_flag), write z,
// and flag at-risk neurons into the per-b bucket. g_hall eliminated.
#define TILE_K 32
#define SLAB_BYTES 8192                   // 128 rows x 64 B
#define STAGE_BYTES (4 * SLAB_BYTES)      // 32 KB
#define SMEM_HDR 1024
#define SMEM_TOTAL (SMEM_HDR + 3 * STAGE_BYTES)   // 99328 B -> 2 CTAs/SM

__global__ void __launch_bounds__(256, 2) gemm_fused_kernel(const float* __restrict__ bias)
{
    extern __shared__ char smem[];
    const uint32_t sb = s2u(smem);
    const int tid = threadIdx.x;
    const int wid = tid >> 5;
    const int lane = tid & 31;
    const int wm = wid >> 2;
    const int wn = wid & 3;

    const int b0 = (int)blockIdx.y;          // batch row
    const int n0 = (int)blockIdx.x * 128;    // h-tile base

    if (tid == 0) {
#pragma unroll
        for (int i = 0; i < 3; i++) {
            MBAR_INIT(sb + 8u * i, 256u);        // full[i]
            MBAR_INIT(sb + 24u + 8u * i, 8u);    // empty[i]
        }
    }
    __syncthreads();

    // A rows: m = t*B + b0 -> plane + (t*B + b0)*D; row stride = B*D
    const __nv_bfloat16* planes[4] = {
        g_Ahi  + (size_t)b0 * D_, g_Amid + (size_t)b0 * D_,
        g_Bhi  + (size_t)n0 * D_, g_Bmid + (size_t)n0 * D_ };
    const size_t rstride[4] = { (size_t)B_ * D_, (size_t)B_ * D_, D_, D_ };

    auto load_stage = [&](int buf, int kBase) {
        const uint32_t base = sb + SMEM_HDR + buf * STAGE_BYTES;
#pragma unroll
        for (int j = 0; j < 4; j++) {
            const __nv_bfloat16* p = planes[j];
            const size_t rs = rstride[j];
            const uint32_t slab = base + j * SLAB_BYTES;
#pragma unroll
            for (int i = 0; i < 2; i++) {
                const int chunk = i * 256 + tid;   // 0..511 (16B chunks)
                const int row = chunk >> 2;        // 0..127 (t for A, h for B)
                const int cc = chunk & 3;          // 0..3
                const uint32_t dst = slab + SWZ64(row * 64 + cc * 16);
                const void* src = p + (size_t)row * rs + kBase + cc * 8;
                asm volatile("cp.async.cg.shared.global [%0], [%1], 16;" :: "r"(dst), "l"(src));
            }
        }
    };

    float acc[4][4][4];
#pragma unroll
    for (int a = 0; a < 4; a++)
#pragma unroll
        for (int b = 0; b < 4; b++)
#pragma unroll
            for (int r = 0; r < 4; r++) acc[a][b][r] = 0.0f;

    load_stage(0, 0);
    CPASYNC_ARRIVE(sb + 0u);
    load_stage(1, TILE_K);
    CPASYNC_ARRIVE(sb + 8u);

    const int aRow = (lane & 15);
    const int aCh  = (lane >> 4);
    const int bRow = (lane & 7) + ((lane >> 4) << 3);
    const int bCh  = (lane >> 3) & 1;

    const int NSTAGE = D_ / TILE_K;   // 16
    for (int s = 0; s < NSTAGE; s++) {
        const int st = s + 2;
        if (st < NSTAGE) {
            const int fb = st % 3;
            if (st >= 3) {
                const uint32_t r = (uint32_t)(st / 3);
                MBAR_WAIT(sb + 24u + 8u * fb, (r - 1u) & 1u);
            }
            load_stage(fb, st * TILE_K);
            CPASYNC_ARRIVE(sb + 8u * fb);
        }

        const int cb = s % 3;
        MBAR_WAIT(sb + 8u * cb, (uint32_t)(s / 3) & 1u);

        const uint32_t stg = sb + SMEM_HDR + (uint32_t)cb * STAGE_BYTES;
#pragma unroll
        for (int kk = 0; kk < 2; kk++) {
            uint32_t Bf[2][8];
#pragma unroll
            for (int pb = 0; pb < 2; pb++) {
                const uint32_t slab = stg + (2 + pb) * SLAB_BYTES;
#pragma unroll
                for (int nt2 = 0; nt2 < 2; nt2++) {
                    const int row = wn * 32 + nt2 * 16 + bRow;
                    const uint32_t ad = slab + SWZ64(row * 64 + kk * 32 + bCh * 16);
                    LDSM4(&Bf[pb][nt2 * 4], ad);
                }
            }
#pragma unroll
            for (int pa = 0; pa < 2; pa++) {
                uint32_t Af[4][4];
                const uint32_t slab = stg + pa * SLAB_BYTES;
#pragma unroll
                for (int mt = 0; mt < 4; mt++) {
                    const int row = wm * 64 + mt * 16 + aRow;
                    const uint32_t ad = slab + SWZ64(row * 64 + kk * 32 + aCh * 16);
                    LDSM4(Af[mt], ad);
                }
                if (kk == 1 && pa == 1 && lane == 0)
                    MBAR_ARRIVE(sb + 24u + 8u * cb);
                const int nProd = 2 - pa;
#pragma unroll
                for (int pb = 0; pb < 2; pb++) {
                    if (pb >= nProd) break;
#pragma unroll
                    for (int mt = 0; mt < 4; mt++) {
#pragma unroll
                        for (int nt2 = 0; nt2 < 2; nt2++) {
                            MMA16816(acc[mt][nt2 * 2 + 0], Af[mt], &Bf[pb][nt2 * 4 + 0]);
                            MMA16816(acc[mt][nt2 * 2 + 1], Af[mt], &Bf[pb][nt2 * 4 + 2]);
                        }
                    }
                }
            }
        }
    }

    // ---- fused epilogue: transpose acc+bias into smem, scan over t ----
    __syncthreads();   // all LDSM done; pipeline buffers are dead
    float* hb = (float*)(smem + SMEM_HDR);   // hb[h][t], stride 129; 66048 B

    const int rBase = wm * 64 + (lane >> 2);        // t within tile
    const int cBase = wn * 32 + 2 * (lane & 3);     // h within tile
#pragma unroll
    for (int mt = 0; mt < 4; mt++) {
#pragma unroll
        for (int nt = 0; nt < 4; nt++) {
            const int col = cBase + nt * 8;
            const float bv0 = bias[n0 + col], bv1 = bias[n0 + col + 1];
            const int r0 = rBase + mt * 16;
            hb[(col    ) * 129 + r0    ] = acc[mt][nt][0] + bv0;
            hb[(col + 1) * 129 + r0    ] = acc[mt][nt][1] + bv1;
            hb[(col    ) * 129 + r0 + 8] = acc[mt][nt][2] + bv0;
            hb[(col + 1) * 129 + r0 + 8] = acc[mt][nt][3] + bv1;
        }
    }
    __syncthreads();

    if (tid < 128) {
        const float* hp = hb + tid * 129;
        float v = 0.0f, z = 0.0f, mm = 1e9f;
#pragma unroll 4
        for (int t = 0; t < T_; t++) {
            v = 0.9f * v + hp[t];
            const float d = v - 1.0f;
            mm = fminf(mm, fabsf(d));
            z = (d > 0.0f) ? 1.0f : 0.0f;
            v -= z;
        }
        g_z[(size_t)b0 * H_ + n0 + tid] = z;
        if (mm < DELTA) {
            const unsigned int p2 = atomicAdd(&g_bcnt[b0], 1u);
            if (p2 < CAPB) g_blist[b0 * CAPB + p2] = b0 * H_ + n0 + tid;
        }
    }
}

// ---------------- fixup: exact h + scan, natural layouts, NHG=32 ----------------
#define FIX_KT 64

__global__ void __launch_bounds__(128) fixup_kernel(const float* __restrict__ x,
                                                    const float* __restrict__ W,
                                                    const float* __restrict__ bias)
{
    __shared__ float xs[T_][FIX_KT + 4];
    __shared__ float ws[NHG][FIX_KT + 4];
    __shared__ float hb[NHG][129];
    __shared__ int hsm[NHG];
    __shared__ int fsm[NHG];

    const int b = blockIdx.x;
    const unsigned int cnt = min(g_bcnt[b], (unsigned int)CAPB);
    if (cnt == 0) return;
    const int tid = threadIdx.x;
    const int jg = tid & 7;
    const int tg = tid >> 3;
    const int t0 = tg * 8;
    const int j0 = jg * 4;

    for (unsigned int g = 0; g < cnt; g += NHG) {
        const int nh = (int)min((unsigned int)NHG, cnt - g);
        if (tid < NHG) {
            const int fl = (tid < nh) ? g_blist[b * CAPB + g + tid] : -1;
            fsm[tid] = fl;
            hsm[tid] = (fl >= 0) ? (fl % H_) : 0;
        }
        __syncthreads();

        float acc[8][4];
#pragma unroll
        for (int i = 0; i < 8; i++)
#pragma unroll
            for (int j = 0; j < 4; j++) acc[i][j] = 0.0f;

        for (int kt = 0; kt < D_ / FIX_KT; kt++) {
            const int k0 = kt * FIX_KT;
#pragma unroll
            for (int i = 0; i < 16; i++) {
                const int idx = i * 128 + tid;
                const int t = idx >> 4;
                const int c4 = idx & 15;
                const float4 v = *(const float4*)(x + ((size_t)t * B_ + b) * D_ + k0 + c4 * 4);
                *(float4*)&xs[t][c4 * 4] = v;
            }
#pragma unroll
            for (int i = 0; i < 4; i++) {
                const int idx = i * 128 + tid;
                const int j = idx >> 4;
                const int c4 = idx & 15;
                float4 wv = make_float4(0.f, 0.f, 0.f, 0.f);
                if (j < nh)
                    wv = *(const float4*)(W + (size_t)hsm[j] * D_ + k0 + c4 * 4);
                *(float4*)&ws[j][c4 * 4] = wv;
            }
            __syncthreads();

#pragma unroll
            for (int kc = 0; kc < FIX_KT / 4; kc++) {
                float4 wv[4];
#pragma unroll
                for (int jj = 0; jj < 4; jj++)
                    wv[jj] = *(const float4*)&ws[j0 + jj][kc * 4];
#pragma unroll
                for (int i = 0; i < 8; i++) {
                    const float4 xv = *(const float4*)&xs[t0 + i][kc * 4];
#pragma unroll
                    for (int jj = 0; jj < 4; jj++) {
                        acc[i][jj] = fmaf(xv.x, wv[jj].x, acc[i][jj]);
                        acc[i][jj] = fmaf(xv.y, wv[jj].y, acc[i][jj]);
                        acc[i][jj] = fmaf(xv.z, wv[jj].z, acc[i][jj]);
                        acc[i][jj] = fmaf(xv.w, wv[jj].w, acc[i][jj]);
                    }
                }
            }
            __syncthreads();
        }

#pragma unroll
        for (int jj = 0; jj < 4; jj++) {
            const float bv = bias[hsm[j0 + jj]];
#pragma unroll
            for (int i = 0; i < 8; i++)
                hb[j0 + jj][t0 + i] = acc[i][jj] + bv;
        }
        __syncthreads();

        if (tid < nh) {
            const float* hp = hb[tid];
            float v = 0.0f, z = 0.0f;
#pragma unroll 4
            for (int t = 0; t < T_; t++) {
                v = 0.9f * v + hp[t];
                z = (v > 1.0f) ? 1.0f : 0.0f;
                v -= z;
            }
            g_z[fsm[tid]] = z;
        }
        __syncthreads();
    }
}

// ---------------- classifier ----------------
__global__ void __launch_bounds__(256) cls_kernel(const float* __restrict__ Wout,
                                                  const float* __restrict__ bout,
                                                  float* __restrict__ out)
{
    const int gw = (blockIdx.x * blockDim.x + threadIdx.x) >> 5;
    const int lane = threadIdx.x & 31;
    if (gw >= B_ * C_) return;
    const int b = gw / C_;
    const int c = gw % C_;

    const float* zp = g_z + (size_t)b * H_;
    const float* wp = Wout + (size_t)c * H_;

    float s = 0.0f;
#pragma unroll
    for (int h = lane * 4; h < H_; h += 32 * 4) {
        const float4 zz = *(const float4*)&zp[h];
        const float4 ww = *(const float4*)&wp[h];
        s = fmaf(zz.x, ww.x, s);
        s = fmaf(zz.y, ww.y, s);
        s = fmaf(zz.z, ww.z, s);
        s = fmaf(zz.w, ww.w, s);
    }
#pragma unroll
    for (int o = 16; o > 0; o >>= 1)
        s += __shfl_xor_sync(0xffffffffu, s, o);
    if (lane == 0) out[(size_t)b * C_ + c] = s + bout[c];
}

// ---------------------------------------------------------------------------
extern "C" void kernel_launch(void* const* d_in, const int* in_sizes, int n_in,
                              void* d_out, int out_size)
{
    const float* x     = (const float*)d_in[0];  // [T, B, D]
    const float* W_in  = (const float*)d_in[1];  // [H, D]
    const float* b_in  = (const float*)d_in[2];  // [H]
    const float* W_out = (const float*)d_in[3];  // [C, H]
    const float* b_out = (const float*)d_in[4];  // [C]
    float* out = (float*)d_out;                  // [B, C]

    cudaFuncSetAttribute(gemm_fused_kernel, cudaFuncAttributeMaxDynamicSharedMemorySize, SMEM_TOTAL);

    zero_cnt_kernel<<<1, 512>>>();
    splitA_kernel<<<(M_ * D_ / 4 + 255) / 256, 256>>>(x);
    splitB_kernel<<<(H_ * D_ / 4 + 255) / 256, 256>>>(W_in);

    dim3 g(H_ / 128, B_);                        // 16 x 512 CTAs
    gemm_fused_kernel<<<g, 256, SMEM_TOTAL>>>(b_in);

    fixup_kernel<<<B_, 128>>>(x, W_in, b_in);

    cls_kernel<<<(B_ * C_ * 32) / 256, 256>>>(W_out, b_out, out);
}